// round 1
// baseline (speedup 1.0000x reference)
#include <cuda_runtime.h>
#include <cuda_bf16.h>
#include <cstdint>

// ---------------------------------------------------------------------------
// Problem constants
//   x  [2, 2048, 2048]  fp32
//   Wq [2048, 2048], Wk/Wv [2048, 512], Wo [2048, 2048]
//   H=16, KVH=4, DH=128, group g=4, causal attention, QK RMSNorm (eps 1e-8)
// ---------------------------------------------------------------------------
#define BATCH 2
#define SEQ   2048
#define DMODEL 2048
#define KVD    512
#define NHEAD  16
#define NKVH   4
#define DHEAD  128

// Scratch buffers (allocation-free rule: __device__ globals)
__device__ float g_Q[BATCH * SEQ * DMODEL];  // 32 MB
__device__ float g_K[BATCH * SEQ * KVD];     //  8 MB
__device__ float g_V[BATCH * SEQ * KVD];     //  8 MB
__device__ float g_O[BATCH * SEQ * DMODEL];  // 32 MB

// ---------------------------------------------------------------------------
// SGEMM: C[M,N] = A[M,K] @ B[K,N]  (+ optional residual R[M,N])
// 128x128 block tile, BK=8, 256 threads, 8x8 per-thread microtile.
// All dims are multiples of the tile sizes for this problem.
// ---------------------------------------------------------------------------
__global__ __launch_bounds__(256)
void sgemm128(int M, int N, int K,
              const float* __restrict__ A,
              const float* __restrict__ B,
              const float* __restrict__ R,   // nullable residual
              float* __restrict__ C) {
    constexpr int BM = 128, BN = 128, BK = 8, TM = 8, TN = 8;
    const int cRow = blockIdx.y;
    const int cCol = blockIdx.x;
    const int threadCol = threadIdx.x % (BN / TN);   // 0..15
    const int threadRow = threadIdx.x / (BN / TN);   // 0..15

    __shared__ float As[BK * BM];   // transposed A tile
    __shared__ float Bs[BK * BN];

    A += (size_t)cRow * BM * K;
    B += cCol * BN;

    const int innerRowA = threadIdx.x >> 1;              // 0..127
    const int innerColA = (threadIdx.x & 1) * 4;         // 0 or 4
    const int innerRowB = threadIdx.x >> 5;              // 0..7
    const int innerColB = (threadIdx.x & 31) * 4;        // 0..124

    float acc[TM * TN];
    #pragma unroll
    for (int i = 0; i < TM * TN; i++) acc[i] = 0.f;
    float regM[TM], regN[TN];

    for (int bk = 0; bk < K; bk += BK) {
        float4 a4 = *(const float4*)(A + (size_t)innerRowA * K + innerColA);
        As[(innerColA + 0) * BM + innerRowA] = a4.x;
        As[(innerColA + 1) * BM + innerRowA] = a4.y;
        As[(innerColA + 2) * BM + innerRowA] = a4.z;
        As[(innerColA + 3) * BM + innerRowA] = a4.w;
        *(float4*)(Bs + innerRowB * BN + innerColB) =
            *(const float4*)(B + (size_t)innerRowB * N + innerColB);
        __syncthreads();
        A += BK;
        B += (size_t)BK * N;

        #pragma unroll
        for (int k = 0; k < BK; k++) {
            *(float4*)(regM)     = *(const float4*)(As + k * BM + threadRow * TM);
            *(float4*)(regM + 4) = *(const float4*)(As + k * BM + threadRow * TM + 4);
            *(float4*)(regN)     = *(const float4*)(Bs + k * BN + threadCol * TN);
            *(float4*)(regN + 4) = *(const float4*)(Bs + k * BN + threadCol * TN + 4);
            #pragma unroll
            for (int i = 0; i < TM; i++)
                #pragma unroll
                for (int j = 0; j < TN; j++)
                    acc[i * TN + j] += regM[i] * regN[j];
        }
        __syncthreads();
    }

    #pragma unroll
    for (int i = 0; i < TM; i++) {
        const int row = cRow * BM + threadRow * TM + i;
        float* Crow = C + (size_t)row * N + cCol * BN + threadCol * TN;
        #pragma unroll
        for (int j = 0; j < TN; j += 4) {
            float4 o = make_float4(acc[i * TN + j], acc[i * TN + j + 1],
                                   acc[i * TN + j + 2], acc[i * TN + j + 3]);
            if (R) {
                const float4 rr = *(const float4*)(R + (size_t)row * N + cCol * BN + threadCol * TN + j);
                o.x += rr.x; o.y += rr.y; o.z += rr.z; o.w += rr.w;
            }
            *(float4*)(Crow + j) = o;
        }
    }
}

// ---------------------------------------------------------------------------
// RMSNorm over contiguous 128-float vectors: one warp per vector
// ---------------------------------------------------------------------------
__global__ __launch_bounds__(256)
void rmsnorm128(float* __restrict__ t, const float* __restrict__ gamma, int nvec) {
    const int w = (blockIdx.x * blockDim.x + threadIdx.x) >> 5;
    if (w >= nvec) return;
    const int lane = threadIdx.x & 31;
    float4* p = (float4*)(t + (size_t)w * DHEAD) + lane;
    float4 v = *p;
    float ss = v.x * v.x + v.y * v.y + v.z * v.z + v.w * v.w;
    #pragma unroll
    for (int o = 16; o; o >>= 1) ss += __shfl_xor_sync(0xffffffffu, ss, o);
    const float rs = rsqrtf(ss * (1.0f / 128.0f) + 1e-8f);
    const float4 gg = ((const float4*)gamma)[lane];
    v.x *= rs * gg.x; v.y *= rs * gg.y; v.z *= rs * gg.z; v.w *= rs * gg.w;
    *p = v;
}

// ---------------------------------------------------------------------------
// Flash-attention (fp32, causal, GQA): BQ=64 rows/CTA, BKV=64 per tile.
// 256 threads. Thread t owns row r = t/4, column-group cg = t%4.
//   QK^T: thread computes 16 scores, cols {cg*4 + 16*jj + j}
//   softmax: online, per quad (4 threads share a row), registers only
//   PV: thread owns 32 output cols, chunks {cg + 4*i} (float4 units)
// smem: Qs[64][129] | S[64][68] | KV (KT[128][68] then reused as Vs[64][128])
// ---------------------------------------------------------------------------
#define FA_SMEM_FLOATS (64 * 129 + 64 * 68 + 128 * 68)

__global__ __launch_bounds__(256)
void flash_fp32(const float* __restrict__ Qb,
                const float* __restrict__ Kb,
                const float* __restrict__ Vb,
                float* __restrict__ Ob) {
    const int qb = blockIdx.x;        // q tile index (0..31)
    const int h  = blockIdx.y;        // head
    const int b  = blockIdx.z;        // batch
    const int kvh = h >> 2;           // GQA: kv head = h / 4

    extern __shared__ float sm[];
    float* Qs = sm;                    // [64][129]
    float* Ssm = Qs + 64 * 129;        // [64][68]
    float* KV  = Ssm + 64 * 68;        // KT [128][68]  /  Vs [64][128]

    const int tid = threadIdx.x;
    const int r   = tid >> 2;          // 0..63
    const int cg  = tid & 3;           // 0..3
    const int q0  = qb * 64;

    // --- load + pre-scale Q tile ---
    const float* Qg = Qb + ((size_t)(b * SEQ + q0) * DMODEL) + h * DHEAD;
    for (int i = tid; i < 64 * 128; i += 256) {
        const int rr = i >> 7, kk = i & 127;
        Qs[rr * 129 + kk] = Qg[(size_t)rr * DMODEL + kk] * 0.08838834764831845f; // DH^-0.5
    }

    float m = -1e30f, l = 0.f;
    float acc[32];
    #pragma unroll
    for (int i = 0; i < 32; i++) acc[i] = 0.f;

    const int qglob = q0 + r;

    for (int kt = 0; kt <= qb; kt++) {
        const int kv0 = kt * 64;
        __syncthreads();   // prior PV done / Q ready (first iter)

        // --- load K tile transposed: KT[d][s], stride 68 ---
        const float* Kg = Kb + ((size_t)(b * SEQ + kv0) * KVD) + kvh * DHEAD;
        for (int i = tid; i < 64 * 128; i += 256) {
            const int ss = i >> 7, dd = i & 127;
            KV[dd * 68 + ss] = Kg[(size_t)ss * KVD + dd];
        }
        __syncthreads();

        // --- S = Q K^T (16 cols per thread) ---
        float s[16];
        #pragma unroll
        for (int i = 0; i < 16; i++) s[i] = 0.f;
        #pragma unroll 4
        for (int k = 0; k < 128; k++) {
            const float qv = Qs[r * 129 + k];
            const float4* KT4 = (const float4*)(KV + k * 68);
            #pragma unroll
            for (int jj = 0; jj < 4; jj++) {
                const float4 kv4 = KT4[cg + 4 * jj];
                s[jj * 4 + 0] += qv * kv4.x;
                s[jj * 4 + 1] += qv * kv4.y;
                s[jj * 4 + 2] += qv * kv4.z;
                s[jj * 4 + 3] += qv * kv4.w;
            }
        }

        // --- causal mask (only diagonal tile can mask) ---
        if (kt == qb) {
            #pragma unroll
            for (int jj = 0; jj < 4; jj++)
                #pragma unroll
                for (int j = 0; j < 4; j++) {
                    const int col = kv0 + cg * 4 + jj * 16 + j;
                    if (col > qglob) s[jj * 4 + j] = -1e30f;
                }
        }

        // --- online softmax, quad-parallel (4 threads per row) ---
        float mx = s[0];
        #pragma unroll
        for (int i = 1; i < 16; i++) mx = fmaxf(mx, s[i]);
        mx = fmaxf(mx, __shfl_xor_sync(0xffffffffu, mx, 1));
        mx = fmaxf(mx, __shfl_xor_sync(0xffffffffu, mx, 2));
        const float mnew = fmaxf(m, mx);
        const float alpha = __expf(m - mnew);
        float ls = 0.f;
        #pragma unroll
        for (int i = 0; i < 16; i++) { s[i] = __expf(s[i] - mnew); ls += s[i]; }
        ls += __shfl_xor_sync(0xffffffffu, ls, 1);
        ls += __shfl_xor_sync(0xffffffffu, ls, 2);
        l = l * alpha + ls;
        m = mnew;

        // write P to smem (thread's 16 cols = 4 contiguous float4 chunks)
        float4* S4 = (float4*)(Ssm + r * 68);
        #pragma unroll
        for (int jj = 0; jj < 4; jj++)
            S4[cg + 4 * jj] = make_float4(s[jj * 4 + 0], s[jj * 4 + 1],
                                          s[jj * 4 + 2], s[jj * 4 + 3]);

        // rescale running output
        #pragma unroll
        for (int i = 0; i < 32; i++) acc[i] *= alpha;

        __syncthreads();   // P written, KT reads complete

        // --- load V tile (row-major [64][128]) into same buffer ---
        const float* Vg = Vb + ((size_t)(b * SEQ + kv0) * KVD) + kvh * DHEAD;
        for (int i = tid; i < 64 * 128; i += 256) {
            const int ss = i >> 7, dd = i & 127;
            KV[ss * 128 + dd] = Vg[(size_t)ss * KVD + dd];
        }
        __syncthreads();

        // --- O += P @ V ---
        #pragma unroll 4
        for (int kk = 0; kk < 64; kk++) {
            const float p = Ssm[r * 68 + kk];
            const float4* V4 = (const float4*)(KV + kk * 128);
            #pragma unroll
            for (int i = 0; i < 8; i++) {
                const float4 v = V4[cg + 4 * i];
                acc[i * 4 + 0] += p * v.x;
                acc[i * 4 + 1] += p * v.y;
                acc[i * 4 + 2] += p * v.z;
                acc[i * 4 + 3] += p * v.w;
            }
        }
    }

    // --- epilogue: normalize and write to g_O laid out [b, q, h*128 + d] ---
    const float inv = 1.0f / l;
    float* Og = Ob + ((size_t)(b * SEQ + q0 + r) * DMODEL) + h * DHEAD;
    #pragma unroll
    for (int i = 0; i < 8; i++) {
        const int c4 = cg + 4 * i;
        *(float4*)(Og + c4 * 4) = make_float4(acc[i * 4 + 0] * inv, acc[i * 4 + 1] * inv,
                                              acc[i * 4 + 2] * inv, acc[i * 4 + 3] * inv);
    }
}

// ---------------------------------------------------------------------------
// launch
// ---------------------------------------------------------------------------
extern "C" void kernel_launch(void* const* d_in, const int* in_sizes, int n_in,
                              void* d_out, int out_size) {
    const float* x  = (const float*)d_in[0];
    const float* Wq = (const float*)d_in[1];
    const float* Wk = (const float*)d_in[2];
    const float* Wv = (const float*)d_in[3];
    const float* Wo = (const float*)d_in[4];
    const float* qg = (const float*)d_in[5];
    const float* kg = (const float*)d_in[6];
    float* out = (float*)d_out;

    float *pQ, *pK, *pV, *pO;
    cudaGetSymbolAddress((void**)&pQ, g_Q);
    cudaGetSymbolAddress((void**)&pK, g_K);
    cudaGetSymbolAddress((void**)&pV, g_V);
    cudaGetSymbolAddress((void**)&pO, g_O);

    const int M = BATCH * SEQ;  // 4096

    // QKV projections
    sgemm128<<<dim3(DMODEL / 128, M / 128), 256>>>(M, DMODEL, DMODEL, x, Wq, nullptr, pQ);
    sgemm128<<<dim3(KVD    / 128, M / 128), 256>>>(M, KVD,    DMODEL, x, Wk, nullptr, pK);
    sgemm128<<<dim3(KVD    / 128, M / 128), 256>>>(M, KVD,    DMODEL, x, Wv, nullptr, pV);

    // per-head RMSNorm (Q: 4096*16 vectors, K: 4096*4 vectors of 128)
    rmsnorm128<<<(M * NHEAD) / 8, 256>>>(pQ, qg, M * NHEAD);
    rmsnorm128<<<(M * NKVH)  / 8, 256>>>(pK, kg, M * NKVH);

    // causal GQA flash attention
    const size_t smem = FA_SMEM_FLOATS * sizeof(float);
    cudaFuncSetAttribute(flash_fp32, cudaFuncAttributeMaxDynamicSharedMemorySize, (int)smem);
    flash_fp32<<<dim3(SEQ / 64, NHEAD, BATCH), 256, smem>>>(pQ, pK, pV, pO);

    // output projection + residual
    sgemm128<<<dim3(DMODEL / 128, M / 128), 256>>>(M, DMODEL, DMODEL, pO, Wo, x, out);
}

// round 2
// speedup vs baseline: 1.4968x; 1.4968x over previous
#include <cuda_runtime.h>
#include <cuda_bf16.h>
#include <cstdint>

// ---------------------------------------------------------------------------
// Problem constants
// ---------------------------------------------------------------------------
#define BATCH 2
#define SEQ   2048
#define DMODEL 2048
#define KVD    512
#define NHEAD  16
#define NKVH   4
#define DHEAD  128

// Scratch buffers (allocation-free rule: __device__ globals)
__device__ float g_Q[BATCH * SEQ * DMODEL];
__device__ float g_K[BATCH * SEQ * KVD];
__device__ float g_V[BATCH * SEQ * KVD];
__device__ float g_O[BATCH * SEQ * DMODEL];

// ---------------------------------------------------------------------------
// TF32 tensor-core GEMM: C[M,N] = A[M,K] @ B[K,N] (+ optional residual R)
// 128x128x32 CTA tile, 256 threads = 8 warps in 2x4 grid, 64x32 warp tile,
// mma.sync.m16n8k8.tf32, double-buffered smem, register prefetch.
// Inputs rounded to tf32 (cvt.rna) during smem staging.
// smem strides 36 / 132 make all fragment LDS conflict-free.
// ---------------------------------------------------------------------------
#define AS_STRIDE 36
#define BS_STRIDE 132
#define AS_SZ (128 * AS_STRIDE)   // 4608 floats
#define BS_SZ (32 * BS_STRIDE)    // 4224 floats
#define GEMM_SMEM_FLOATS (2 * AS_SZ + 2 * BS_SZ)

__device__ __forceinline__ float tf32r(float x) {
    uint32_t u;
    asm("cvt.rna.tf32.f32 %0, %1;" : "=r"(u) : "f"(x));
    return __uint_as_float(u);
}

__device__ __forceinline__ void mma_tf32(float c[4], const float a[4], const float b[2]) {
    asm volatile(
        "mma.sync.aligned.m16n8k8.row.col.f32.tf32.tf32.f32 "
        "{%0,%1,%2,%3}, {%4,%5,%6,%7}, {%8,%9}, {%0,%1,%2,%3};\n"
        : "+f"(c[0]), "+f"(c[1]), "+f"(c[2]), "+f"(c[3])
        : "r"(__float_as_uint(a[0])), "r"(__float_as_uint(a[1])),
          "r"(__float_as_uint(a[2])), "r"(__float_as_uint(a[3])),
          "r"(__float_as_uint(b[0])), "r"(__float_as_uint(b[1])));
}

__global__ __launch_bounds__(256)
void gemm_tf32(int M, int N, int K,
               const float* __restrict__ A,
               const float* __restrict__ B,
               const float* __restrict__ R,
               float* __restrict__ C) {
    extern __shared__ float sm[];
    float* As = sm;                 // 2 x [128][36]
    float* Bs = sm + 2 * AS_SZ;     // 2 x [32][132]

    const int tid    = threadIdx.x;
    const int lane   = tid & 31;
    const int warpId = tid >> 5;
    const int warpRow = warpId & 1;       // 0..1  (64 rows each)
    const int warpCol = warpId >> 1;      // 0..3  (32 cols each)
    const int grp = lane >> 2;            // 0..7
    const int tig = lane & 3;             // 0..3

    const float* Ablk = A + (size_t)blockIdx.y * 128 * K;
    const float* Bblk = B + blockIdx.x * 128;

    // staging indices (4 float4 loads each for A and B per thread)
    const int aR0 = tid >> 3;             // 0..31, +32 per it
    const int aC0 = (tid & 7) * 4;        // 0..28
    const int bR0 = tid >> 5;             // 0..7, +8 per it
    const int bC0 = (tid & 31) * 4;       // 0..124

    float acc[4][4][4];
    #pragma unroll
    for (int i = 0; i < 4; i++)
        #pragma unroll
        for (int j = 0; j < 4; j++)
            #pragma unroll
            for (int q = 0; q < 4; q++) acc[i][j][q] = 0.f;

    float4 ra[4], rb[4];

    // prologue: tile 0
    #pragma unroll
    for (int it = 0; it < 4; it++) {
        ra[it] = *(const float4*)(Ablk + (size_t)(aR0 + it * 32) * K + aC0);
        rb[it] = *(const float4*)(Bblk + (size_t)(bR0 + it * 8) * N + bC0);
    }
    #pragma unroll
    for (int it = 0; it < 4; it++) {
        float* pa = As + (aR0 + it * 32) * AS_STRIDE + aC0;
        pa[0] = tf32r(ra[it].x); pa[1] = tf32r(ra[it].y);
        pa[2] = tf32r(ra[it].z); pa[3] = tf32r(ra[it].w);
        float* pb = Bs + (bR0 + it * 8) * BS_STRIDE + bC0;
        pb[0] = tf32r(rb[it].x); pb[1] = tf32r(rb[it].y);
        pb[2] = tf32r(rb[it].z); pb[3] = tf32r(rb[it].w);
    }
    __syncthreads();

    int buf = 0;
    for (int k0 = 0; k0 < K; k0 += 32) {
        const bool more = (k0 + 32) < K;
        if (more) {
            #pragma unroll
            for (int it = 0; it < 4; it++) {
                ra[it] = *(const float4*)(Ablk + (size_t)(aR0 + it * 32) * K + k0 + 32 + aC0);
                rb[it] = *(const float4*)(Bblk + (size_t)(k0 + 32 + bR0 + it * 8) * N + bC0);
            }
        }

        // compute on current buffer
        const float* Ab = As + buf * AS_SZ;
        const float* Bb = Bs + buf * BS_SZ;
        #pragma unroll
        for (int ks = 0; ks < 4; ks++) {
            float afr[4][4], bfr[4][2];
            #pragma unroll
            for (int mt = 0; mt < 4; mt++) {
                const int rb_ = warpRow * 64 + mt * 16 + grp;
                const int cb_ = ks * 8 + tig;
                afr[mt][0] = Ab[(rb_    ) * AS_STRIDE + cb_    ];
                afr[mt][1] = Ab[(rb_ + 8) * AS_STRIDE + cb_    ];
                afr[mt][2] = Ab[(rb_    ) * AS_STRIDE + cb_ + 4];
                afr[mt][3] = Ab[(rb_ + 8) * AS_STRIDE + cb_ + 4];
            }
            #pragma unroll
            for (int nt = 0; nt < 4; nt++) {
                const int cb_ = warpCol * 32 + nt * 8 + grp;
                bfr[nt][0] = Bb[(ks * 8 + tig    ) * BS_STRIDE + cb_];
                bfr[nt][1] = Bb[(ks * 8 + tig + 4) * BS_STRIDE + cb_];
            }
            #pragma unroll
            for (int mt = 0; mt < 4; mt++)
                #pragma unroll
                for (int nt = 0; nt < 4; nt++)
                    mma_tf32(acc[mt][nt], afr[mt], bfr[nt]);
        }

        if (more) {
            const int nb = buf ^ 1;
            #pragma unroll
            for (int it = 0; it < 4; it++) {
                float* pa = As + nb * AS_SZ + (aR0 + it * 32) * AS_STRIDE + aC0;
                pa[0] = tf32r(ra[it].x); pa[1] = tf32r(ra[it].y);
                pa[2] = tf32r(ra[it].z); pa[3] = tf32r(ra[it].w);
                float* pb = Bs + nb * BS_SZ + (bR0 + it * 8) * BS_STRIDE + bC0;
                pb[0] = tf32r(rb[it].x); pb[1] = tf32r(rb[it].y);
                pb[2] = tf32r(rb[it].z); pb[3] = tf32r(rb[it].w);
            }
        }
        __syncthreads();
        buf ^= 1;
    }

    // epilogue: c0 (row, col), c1 (row, col+1), c2 (row+8, col), c3 (row+8, col+1)
    #pragma unroll
    for (int mt = 0; mt < 4; mt++) {
        #pragma unroll
        for (int nt = 0; nt < 4; nt++) {
            const int row = blockIdx.y * 128 + warpRow * 64 + mt * 16 + grp;
            const int col = blockIdx.x * 128 + warpCol * 32 + nt * 8 + 2 * tig;
            float2 v0 = make_float2(acc[mt][nt][0], acc[mt][nt][1]);
            float2 v1 = make_float2(acc[mt][nt][2], acc[mt][nt][3]);
            if (R) {
                const float2 r0 = *(const float2*)(R + (size_t)row * N + col);
                const float2 r1 = *(const float2*)(R + (size_t)(row + 8) * N + col);
                v0.x += r0.x; v0.y += r0.y;
                v1.x += r1.x; v1.y += r1.y;
            }
            *(float2*)(C + (size_t)row * N + col) = v0;
            *(float2*)(C + (size_t)(row + 8) * N + col) = v1;
        }
    }
}

// ---------------------------------------------------------------------------
// RMSNorm over contiguous 128-float vectors: one warp per vector
// ---------------------------------------------------------------------------
__global__ __launch_bounds__(256)
void rmsnorm128(float* __restrict__ t, const float* __restrict__ gamma, int nvec) {
    const int w = (blockIdx.x * blockDim.x + threadIdx.x) >> 5;
    if (w >= nvec) return;
    const int lane = threadIdx.x & 31;
    float4* p = (float4*)(t + (size_t)w * DHEAD) + lane;
    float4 v = *p;
    float ss = v.x * v.x + v.y * v.y + v.z * v.z + v.w * v.w;
    #pragma unroll
    for (int o = 16; o; o >>= 1) ss += __shfl_xor_sync(0xffffffffu, ss, o);
    const float rs = rsqrtf(ss * (1.0f / 128.0f) + 1e-8f);
    const float4 gg = ((const float4*)gamma)[lane];
    v.x *= rs * gg.x; v.y *= rs * gg.y; v.z *= rs * gg.z; v.w *= rs * gg.w;
    *p = v;
}

// ---------------------------------------------------------------------------
// Flash-attention (fp32, causal, GQA): unchanged from R1 (passing)
// ---------------------------------------------------------------------------
#define FA_SMEM_FLOATS (64 * 129 + 64 * 68 + 128 * 68)

__global__ __launch_bounds__(256)
void flash_fp32(const float* __restrict__ Qb,
                const float* __restrict__ Kb,
                const float* __restrict__ Vb,
                float* __restrict__ Ob) {
    const int qb = blockIdx.x;
    const int h  = blockIdx.y;
    const int b  = blockIdx.z;
    const int kvh = h >> 2;

    extern __shared__ float sm[];
    float* Qs = sm;
    float* Ssm = Qs + 64 * 129;
    float* KV  = Ssm + 64 * 68;

    const int tid = threadIdx.x;
    const int r   = tid >> 2;
    const int cg  = tid & 3;
    const int q0  = qb * 64;

    const float* Qg = Qb + ((size_t)(b * SEQ + q0) * DMODEL) + h * DHEAD;
    for (int i = tid; i < 64 * 128; i += 256) {
        const int rr = i >> 7, kk = i & 127;
        Qs[rr * 129 + kk] = Qg[(size_t)rr * DMODEL + kk] * 0.08838834764831845f;
    }

    float m = -1e30f, l = 0.f;
    float acc[32];
    #pragma unroll
    for (int i = 0; i < 32; i++) acc[i] = 0.f;

    const int qglob = q0 + r;

    for (int kt = 0; kt <= qb; kt++) {
        const int kv0 = kt * 64;
        __syncthreads();

        const float* Kg = Kb + ((size_t)(b * SEQ + kv0) * KVD) + kvh * DHEAD;
        for (int i = tid; i < 64 * 128; i += 256) {
            const int ss = i >> 7, dd = i & 127;
            KV[dd * 68 + ss] = Kg[(size_t)ss * KVD + dd];
        }
        __syncthreads();

        float s[16];
        #pragma unroll
        for (int i = 0; i < 16; i++) s[i] = 0.f;
        #pragma unroll 4
        for (int k = 0; k < 128; k++) {
            const float qv = Qs[r * 129 + k];
            const float4* KT4 = (const float4*)(KV + k * 68);
            #pragma unroll
            for (int jj = 0; jj < 4; jj++) {
                const float4 kv4 = KT4[cg + 4 * jj];
                s[jj * 4 + 0] += qv * kv4.x;
                s[jj * 4 + 1] += qv * kv4.y;
                s[jj * 4 + 2] += qv * kv4.z;
                s[jj * 4 + 3] += qv * kv4.w;
            }
        }

        if (kt == qb) {
            #pragma unroll
            for (int jj = 0; jj < 4; jj++)
                #pragma unroll
                for (int j = 0; j < 4; j++) {
                    const int col = kv0 + cg * 4 + jj * 16 + j;
                    if (col > qglob) s[jj * 4 + j] = -1e30f;
                }
        }

        float mx = s[0];
        #pragma unroll
        for (int i = 1; i < 16; i++) mx = fmaxf(mx, s[i]);
        mx = fmaxf(mx, __shfl_xor_sync(0xffffffffu, mx, 1));
        mx = fmaxf(mx, __shfl_xor_sync(0xffffffffu, mx, 2));
        const float mnew = fmaxf(m, mx);
        const float alpha = __expf(m - mnew);
        float ls = 0.f;
        #pragma unroll
        for (int i = 0; i < 16; i++) { s[i] = __expf(s[i] - mnew); ls += s[i]; }
        ls += __shfl_xor_sync(0xffffffffu, ls, 1);
        ls += __shfl_xor_sync(0xffffffffu, ls, 2);
        l = l * alpha + ls;
        m = mnew;

        float4* S4 = (float4*)(Ssm + r * 68);
        #pragma unroll
        for (int jj = 0; jj < 4; jj++)
            S4[cg + 4 * jj] = make_float4(s[jj * 4 + 0], s[jj * 4 + 1],
                                          s[jj * 4 + 2], s[jj * 4 + 3]);

        #pragma unroll
        for (int i = 0; i < 32; i++) acc[i] *= alpha;

        __syncthreads();

        const float* Vg = Vb + ((size_t)(b * SEQ + kv0) * KVD) + kvh * DHEAD;
        for (int i = tid; i < 64 * 128; i += 256) {
            const int ss = i >> 7, dd = i & 127;
            KV[ss * 128 + dd] = Vg[(size_t)ss * KVD + dd];
        }
        __syncthreads();

        #pragma unroll 4
        for (int kk = 0; kk < 64; kk++) {
            const float p = Ssm[r * 68 + kk];
            const float4* V4 = (const float4*)(KV + kk * 128);
            #pragma unroll
            for (int i = 0; i < 8; i++) {
                const float4 v = V4[cg + 4 * i];
                acc[i * 4 + 0] += p * v.x;
                acc[i * 4 + 1] += p * v.y;
                acc[i * 4 + 2] += p * v.z;
                acc[i * 4 + 3] += p * v.w;
            }
        }
    }

    const float inv = 1.0f / l;
    float* Og = Ob + ((size_t)(b * SEQ + q0 + r) * DMODEL) + h * DHEAD;
    #pragma unroll
    for (int i = 0; i < 8; i++) {
        const int c4 = cg + 4 * i;
        *(float4*)(Og + c4 * 4) = make_float4(acc[i * 4 + 0] * inv, acc[i * 4 + 1] * inv,
                                              acc[i * 4 + 2] * inv, acc[i * 4 + 3] * inv);
    }
}

// ---------------------------------------------------------------------------
// launch
// ---------------------------------------------------------------------------
extern "C" void kernel_launch(void* const* d_in, const int* in_sizes, int n_in,
                              void* d_out, int out_size) {
    const float* x  = (const float*)d_in[0];
    const float* Wq = (const float*)d_in[1];
    const float* Wk = (const float*)d_in[2];
    const float* Wv = (const float*)d_in[3];
    const float* Wo = (const float*)d_in[4];
    const float* qg = (const float*)d_in[5];
    const float* kg = (const float*)d_in[6];
    float* out = (float*)d_out;

    float *pQ, *pK, *pV, *pO;
    cudaGetSymbolAddress((void**)&pQ, g_Q);
    cudaGetSymbolAddress((void**)&pK, g_K);
    cudaGetSymbolAddress((void**)&pV, g_V);
    cudaGetSymbolAddress((void**)&pO, g_O);

    const int M = BATCH * SEQ;  // 4096

    const size_t gsmem = GEMM_SMEM_FLOATS * sizeof(float);
    cudaFuncSetAttribute(gemm_tf32, cudaFuncAttributeMaxDynamicSharedMemorySize, (int)gsmem);

    // QKV projections (tf32 tensor cores)
    gemm_tf32<<<dim3(DMODEL / 128, M / 128), 256, gsmem>>>(M, DMODEL, DMODEL, x, Wq, nullptr, pQ);
    gemm_tf32<<<dim3(KVD    / 128, M / 128), 256, gsmem>>>(M, KVD,    DMODEL, x, Wk, nullptr, pK);
    gemm_tf32<<<dim3(KVD    / 128, M / 128), 256, gsmem>>>(M, KVD,    DMODEL, x, Wv, nullptr, pV);

    // per-head RMSNorm
    rmsnorm128<<<(M * NHEAD) / 8, 256>>>(pQ, qg, M * NHEAD);
    rmsnorm128<<<(M * NKVH)  / 8, 256>>>(pK, kg, M * NKVH);

    // causal GQA flash attention (fp32)
    const size_t fsmem = FA_SMEM_FLOATS * sizeof(float);
    cudaFuncSetAttribute(flash_fp32, cudaFuncAttributeMaxDynamicSharedMemorySize, (int)fsmem);
    flash_fp32<<<dim3(SEQ / 64, NHEAD, BATCH), 256, fsmem>>>(pQ, pK, pV, pO);

    // output projection + residual (tf32 tensor cores)
    gemm_tf32<<<dim3(DMODEL / 128, M / 128), 256, gsmem>>>(M, DMODEL, DMODEL, pO, Wo, x, out);
}

// round 3
// speedup vs baseline: 4.8050x; 3.2102x over previous
#include <cuda_runtime.h>
#include <cuda_bf16.h>
#include <cstdint>

// ---------------------------------------------------------------------------
// Problem constants
// ---------------------------------------------------------------------------
#define BATCH 2
#define SEQ   2048
#define DMODEL 2048
#define KVD    512
#define NHEAD  16
#define NKVH   4
#define DHEAD  128

// Scratch buffers (allocation-free rule: __device__ globals)
__device__ float g_Q[BATCH * SEQ * DMODEL];
__device__ float g_K[BATCH * SEQ * KVD];
__device__ float g_V[BATCH * SEQ * KVD];
__device__ float g_O[BATCH * SEQ * DMODEL];

__device__ __forceinline__ float tf32r(float x) {
    uint32_t u;
    asm("cvt.rna.tf32.f32 %0, %1;" : "=r"(u) : "f"(x));
    return __uint_as_float(u);
}

__device__ __forceinline__ void mma_tf32(float c[4], const float a[4], const float b[2]) {
    asm volatile(
        "mma.sync.aligned.m16n8k8.row.col.f32.tf32.tf32.f32 "
        "{%0,%1,%2,%3}, {%4,%5,%6,%7}, {%8,%9}, {%0,%1,%2,%3};\n"
        : "+f"(c[0]), "+f"(c[1]), "+f"(c[2]), "+f"(c[3])
        : "r"(__float_as_uint(a[0])), "r"(__float_as_uint(a[1])),
          "r"(__float_as_uint(a[2])), "r"(__float_as_uint(a[3])),
          "r"(__float_as_uint(b[0])), "r"(__float_as_uint(b[1])));
}

// ---------------------------------------------------------------------------
// TF32 tensor-core GEMM (unchanged from R2, passing at rel_err 5e-5)
// ---------------------------------------------------------------------------
#define AS_STRIDE 36
#define BS_STRIDE 132
#define AS_SZ (128 * AS_STRIDE)
#define BS_SZ (32 * BS_STRIDE)
#define GEMM_SMEM_FLOATS (2 * AS_SZ + 2 * BS_SZ)

__global__ __launch_bounds__(256)
void gemm_tf32(int M, int N, int K,
               const float* __restrict__ A,
               const float* __restrict__ B,
               const float* __restrict__ R,
               float* __restrict__ C) {
    extern __shared__ float sm[];
    float* As = sm;
    float* Bs = sm + 2 * AS_SZ;

    const int tid    = threadIdx.x;
    const int lane   = tid & 31;
    const int warpId = tid >> 5;
    const int warpRow = warpId & 1;
    const int warpCol = warpId >> 1;
    const int grp = lane >> 2;
    const int tig = lane & 3;

    const float* Ablk = A + (size_t)blockIdx.y * 128 * K;
    const float* Bblk = B + blockIdx.x * 128;

    const int aR0 = tid >> 3;
    const int aC0 = (tid & 7) * 4;
    const int bR0 = tid >> 5;
    const int bC0 = (tid & 31) * 4;

    float acc[4][4][4];
    #pragma unroll
    for (int i = 0; i < 4; i++)
        #pragma unroll
        for (int j = 0; j < 4; j++)
            #pragma unroll
            for (int q = 0; q < 4; q++) acc[i][j][q] = 0.f;

    float4 ra[4], rb[4];

    #pragma unroll
    for (int it = 0; it < 4; it++) {
        ra[it] = *(const float4*)(Ablk + (size_t)(aR0 + it * 32) * K + aC0);
        rb[it] = *(const float4*)(Bblk + (size_t)(bR0 + it * 8) * N + bC0);
    }
    #pragma unroll
    for (int it = 0; it < 4; it++) {
        float* pa = As + (aR0 + it * 32) * AS_STRIDE + aC0;
        pa[0] = tf32r(ra[it].x); pa[1] = tf32r(ra[it].y);
        pa[2] = tf32r(ra[it].z); pa[3] = tf32r(ra[it].w);
        float* pb = Bs + (bR0 + it * 8) * BS_STRIDE + bC0;
        pb[0] = tf32r(rb[it].x); pb[1] = tf32r(rb[it].y);
        pb[2] = tf32r(rb[it].z); pb[3] = tf32r(rb[it].w);
    }
    __syncthreads();

    int buf = 0;
    for (int k0 = 0; k0 < K; k0 += 32) {
        const bool more = (k0 + 32) < K;
        if (more) {
            #pragma unroll
            for (int it = 0; it < 4; it++) {
                ra[it] = *(const float4*)(Ablk + (size_t)(aR0 + it * 32) * K + k0 + 32 + aC0);
                rb[it] = *(const float4*)(Bblk + (size_t)(k0 + 32 + bR0 + it * 8) * N + bC0);
            }
        }

        const float* Ab = As + buf * AS_SZ;
        const float* Bb = Bs + buf * BS_SZ;
        #pragma unroll
        for (int ks = 0; ks < 4; ks++) {
            float afr[4][4], bfr[4][2];
            #pragma unroll
            for (int mt = 0; mt < 4; mt++) {
                const int rb_ = warpRow * 64 + mt * 16 + grp;
                const int cb_ = ks * 8 + tig;
                afr[mt][0] = Ab[(rb_    ) * AS_STRIDE + cb_    ];
                afr[mt][1] = Ab[(rb_ + 8) * AS_STRIDE + cb_    ];
                afr[mt][2] = Ab[(rb_    ) * AS_STRIDE + cb_ + 4];
                afr[mt][3] = Ab[(rb_ + 8) * AS_STRIDE + cb_ + 4];
            }
            #pragma unroll
            for (int nt = 0; nt < 4; nt++) {
                const int cb_ = warpCol * 32 + nt * 8 + grp;
                bfr[nt][0] = Bb[(ks * 8 + tig    ) * BS_STRIDE + cb_];
                bfr[nt][1] = Bb[(ks * 8 + tig + 4) * BS_STRIDE + cb_];
            }
            #pragma unroll
            for (int mt = 0; mt < 4; mt++)
                #pragma unroll
                for (int nt = 0; nt < 4; nt++)
                    mma_tf32(acc[mt][nt], afr[mt], bfr[nt]);
        }

        if (more) {
            const int nb = buf ^ 1;
            #pragma unroll
            for (int it = 0; it < 4; it++) {
                float* pa = As + nb * AS_SZ + (aR0 + it * 32) * AS_STRIDE + aC0;
                pa[0] = tf32r(ra[it].x); pa[1] = tf32r(ra[it].y);
                pa[2] = tf32r(ra[it].z); pa[3] = tf32r(ra[it].w);
                float* pb = Bs + nb * BS_SZ + (bR0 + it * 8) * BS_STRIDE + bC0;
                pb[0] = tf32r(rb[it].x); pb[1] = tf32r(rb[it].y);
                pb[2] = tf32r(rb[it].z); pb[3] = tf32r(rb[it].w);
            }
        }
        __syncthreads();
        buf ^= 1;
    }

    #pragma unroll
    for (int mt = 0; mt < 4; mt++) {
        #pragma unroll
        for (int nt = 0; nt < 4; nt++) {
            const int row = blockIdx.y * 128 + warpRow * 64 + mt * 16 + grp;
            const int col = blockIdx.x * 128 + warpCol * 32 + nt * 8 + 2 * tig;
            float2 v0 = make_float2(acc[mt][nt][0], acc[mt][nt][1]);
            float2 v1 = make_float2(acc[mt][nt][2], acc[mt][nt][3]);
            if (R) {
                const float2 r0 = *(const float2*)(R + (size_t)row * N + col);
                const float2 r1 = *(const float2*)(R + (size_t)(row + 8) * N + col);
                v0.x += r0.x; v0.y += r0.y;
                v1.x += r1.x; v1.y += r1.y;
            }
            *(float2*)(C + (size_t)row * N + col) = v0;
            *(float2*)(C + (size_t)(row + 8) * N + col) = v1;
        }
    }
}

// ---------------------------------------------------------------------------
// RMSNorm over contiguous 128-float vectors: one warp per vector
// ---------------------------------------------------------------------------
__global__ __launch_bounds__(256)
void rmsnorm128(float* __restrict__ t, const float* __restrict__ gamma, int nvec) {
    const int w = (blockIdx.x * blockDim.x + threadIdx.x) >> 5;
    if (w >= nvec) return;
    const int lane = threadIdx.x & 31;
    float4* p = (float4*)(t + (size_t)w * DHEAD) + lane;
    float4 v = *p;
    float ss = v.x * v.x + v.y * v.y + v.z * v.z + v.w * v.w;
    #pragma unroll
    for (int o = 16; o; o >>= 1) ss += __shfl_xor_sync(0xffffffffu, ss, o);
    const float rs = rsqrtf(ss * (1.0f / 128.0f) + 1e-8f);
    const float4 gg = ((const float4*)gamma)[lane];
    v.x *= rs * gg.x; v.y *= rs * gg.y; v.z *= rs * gg.z; v.w *= rs * gg.w;
    *p = v;
}

// ---------------------------------------------------------------------------
// TF32 tensor-core flash attention (causal, GQA)
// BQ=128 (8 warps x 16 rows), BKV=64, DH=128.
// Q held in registers as mma A-fragments (loaded once).
// K smem [64][132], V smem [64][136] (conflict-free fragment reads).
// P relayout accumulator->A-operand done in registers via quad shfl.
// ---------------------------------------------------------------------------
#define KS_STRIDE 132
#define VS_STRIDE 136
#define FA_SMEM_FLOATS (64 * KS_STRIDE + 64 * VS_STRIDE)

__global__ __launch_bounds__(256, 1)
void flash_tf32(const float* __restrict__ Qb,
                const float* __restrict__ Kb,
                const float* __restrict__ Vb,
                float* __restrict__ Ob) {
    const int qb = blockIdx.x;          // q tile (0..15), BQ=128
    const int h  = blockIdx.y;
    const int b  = blockIdx.z;
    const int kvh = h >> 2;

    extern __shared__ float sm[];
    float* Ks = sm;                      // [64][132]
    float* Vs = sm + 64 * KS_STRIDE;     // [64][136]

    const int tid  = threadIdx.x;
    const int lane = tid & 31;
    const int w    = tid >> 5;           // warp 0..7 -> q rows [w*16, w*16+16)
    const int grp  = lane >> 2;          // 0..7
    const int tig  = lane & 3;           // 0..3
    const int q0   = qb * 128;

    const int r0g = q0 + w * 16 + grp;   // global q row (and +8)

    // --- load Q fragments into registers (pre-scaled, tf32-rounded) ---
    const float SCALE = 0.08838834764831845f;   // DH^-0.5
    float qf[16][4];
    {
        const float* Qg  = Qb + ((size_t)(b * SEQ + r0g) * DMODEL) + h * DHEAD;
        const float* Qg8 = Qg + 8 * (size_t)DMODEL;
        #pragma unroll
        for (int kt = 0; kt < 16; kt++) {
            qf[kt][0] = tf32r(Qg [kt * 8 + tig    ] * SCALE);
            qf[kt][1] = tf32r(Qg8[kt * 8 + tig    ] * SCALE);
            qf[kt][2] = tf32r(Qg [kt * 8 + tig + 4] * SCALE);
            qf[kt][3] = tf32r(Qg8[kt * 8 + tig + 4] * SCALE);
        }
    }

    float oacc[16][4];
    #pragma unroll
    for (int i = 0; i < 16; i++)
        #pragma unroll
        for (int q = 0; q < 4; q++) oacc[i][q] = 0.f;
    float m0 = -1e30f, m1 = -1e30f, l0 = 0.f, l1 = 0.f;

    const int ntiles = 2 * qb + 2;       // kv tiles of 64 covering [0, q0+128)

    for (int t = 0; t < ntiles; t++) {
        const int kv0 = t * 64;
        __syncthreads();   // previous iteration's smem reads complete

        // --- stage K and V tiles (tf32-rounded) ---
        {
            const float* Kg = Kb + ((size_t)(b * SEQ + kv0) * KVD) + kvh * DHEAD;
            const float* Vg = Vb + ((size_t)(b * SEQ + kv0) * KVD) + kvh * DHEAD;
            #pragma unroll
            for (int i = tid; i < 64 * 32; i += 256) {
                const int row = i >> 5, c4 = (i & 31) * 4;
                float4 kx = *(const float4*)(Kg + (size_t)row * KVD + c4);
                kx.x = tf32r(kx.x); kx.y = tf32r(kx.y);
                kx.z = tf32r(kx.z); kx.w = tf32r(kx.w);
                *(float4*)(Ks + row * KS_STRIDE + c4) = kx;
                float4 vx = *(const float4*)(Vg + (size_t)row * KVD + c4);
                vx.x = tf32r(vx.x); vx.y = tf32r(vx.y);
                vx.z = tf32r(vx.z); vx.w = tf32r(vx.w);
                *(float4*)(Vs + row * VS_STRIDE + c4) = vx;
            }
        }
        __syncthreads();

        // --- S = Q K^T : 8 n-tiles (64 kv cols), 16 k-steps ---
        float s[8][4];
        #pragma unroll
        for (int nt = 0; nt < 8; nt++)
            #pragma unroll
            for (int q = 0; q < 4; q++) s[nt][q] = 0.f;

        #pragma unroll
        for (int kt = 0; kt < 16; kt++) {
            #pragma unroll
            for (int nt = 0; nt < 8; nt++) {
                float bf[2];
                bf[0] = Ks[(nt * 8 + grp) * KS_STRIDE + kt * 8 + tig    ];
                bf[1] = Ks[(nt * 8 + grp) * KS_STRIDE + kt * 8 + tig + 4];
                mma_tf32(s[nt], qf[kt], bf);
            }
        }

        // --- causal mask (only possibly-masked tiles) ---
        if (t >= 2 * qb) {
            #pragma unroll
            for (int nt = 0; nt < 8; nt++) {
                const int col = kv0 + nt * 8 + 2 * tig;
                if (col     > r0g    ) s[nt][0] = -1e30f;
                if (col + 1 > r0g    ) s[nt][1] = -1e30f;
                if (col     > r0g + 8) s[nt][2] = -1e30f;
                if (col + 1 > r0g + 8) s[nt][3] = -1e30f;
            }
        }

        // --- online softmax (rows r0g, r0g+8; quad holds a row's 64 cols) ---
        float mx0 = -1e30f, mx1 = -1e30f;
        #pragma unroll
        for (int nt = 0; nt < 8; nt++) {
            mx0 = fmaxf(mx0, fmaxf(s[nt][0], s[nt][1]));
            mx1 = fmaxf(mx1, fmaxf(s[nt][2], s[nt][3]));
        }
        mx0 = fmaxf(mx0, __shfl_xor_sync(0xffffffffu, mx0, 1));
        mx0 = fmaxf(mx0, __shfl_xor_sync(0xffffffffu, mx0, 2));
        mx1 = fmaxf(mx1, __shfl_xor_sync(0xffffffffu, mx1, 1));
        mx1 = fmaxf(mx1, __shfl_xor_sync(0xffffffffu, mx1, 2));

        const float mn0 = fmaxf(m0, mx0);
        const float mn1 = fmaxf(m1, mx1);
        const float al0 = __expf(m0 - mn0);
        const float al1 = __expf(m1 - mn1);

        float ls0 = 0.f, ls1 = 0.f;
        #pragma unroll
        for (int nt = 0; nt < 8; nt++) {
            s[nt][0] = __expf(s[nt][0] - mn0);
            s[nt][1] = __expf(s[nt][1] - mn0);
            s[nt][2] = __expf(s[nt][2] - mn1);
            s[nt][3] = __expf(s[nt][3] - mn1);
            ls0 += s[nt][0] + s[nt][1];
            ls1 += s[nt][2] + s[nt][3];
        }
        ls0 += __shfl_xor_sync(0xffffffffu, ls0, 1);
        ls0 += __shfl_xor_sync(0xffffffffu, ls0, 2);
        ls1 += __shfl_xor_sync(0xffffffffu, ls1, 1);
        ls1 += __shfl_xor_sync(0xffffffffu, ls1, 2);
        l0 = l0 * al0 + ls0;  m0 = mn0;
        l1 = l1 * al1 + ls1;  m1 = mn1;

        // rescale running output
        #pragma unroll
        for (int nt = 0; nt < 16; nt++) {
            oacc[nt][0] *= al0; oacc[nt][1] *= al0;
            oacc[nt][2] *= al1; oacc[nt][3] *= al1;
        }

        // --- O += P V : relayout P (acc->A frag) via quad shfl, then mma ---
        const int sl0 = (lane & 28) | (tig >> 1);   // source lane, col tig
        const int sl1 = sl0 + 2;                    // source lane, col tig+4
        const bool odd = (tig & 1);
        #pragma unroll
        for (int kt = 0; kt < 8; kt++) {
            float x0 = __shfl_sync(0xffffffffu, s[kt][0], sl0);
            float x1 = __shfl_sync(0xffffffffu, s[kt][1], sl0);
            float x2 = __shfl_sync(0xffffffffu, s[kt][2], sl0);
            float x3 = __shfl_sync(0xffffffffu, s[kt][3], sl0);
            float y0 = __shfl_sync(0xffffffffu, s[kt][0], sl1);
            float y1 = __shfl_sync(0xffffffffu, s[kt][1], sl1);
            float y2 = __shfl_sync(0xffffffffu, s[kt][2], sl1);
            float y3 = __shfl_sync(0xffffffffu, s[kt][3], sl1);
            float af[4];
            af[0] = tf32r(odd ? x1 : x0);
            af[1] = tf32r(odd ? x3 : x2);
            af[2] = tf32r(odd ? y1 : y0);
            af[3] = tf32r(odd ? y3 : y2);
            #pragma unroll
            for (int nt = 0; nt < 16; nt++) {
                float bf[2];
                bf[0] = Vs[(kt * 8 + tig    ) * VS_STRIDE + nt * 8 + grp];
                bf[1] = Vs[(kt * 8 + tig + 4) * VS_STRIDE + nt * 8 + grp];
                mma_tf32(oacc[nt], af, bf);
            }
        }
    }

    // --- epilogue: normalize, write O [b, row, h*128 + col] ---
    const float i0 = 1.0f / l0;
    const float i1 = 1.0f / l1;
    float* Og  = Ob + ((size_t)(b * SEQ + r0g) * DMODEL) + h * DHEAD;
    float* Og8 = Og + 8 * (size_t)DMODEL;
    #pragma unroll
    for (int nt = 0; nt < 16; nt++) {
        const int col = nt * 8 + 2 * tig;
        *(float2*)(Og  + col) = make_float2(oacc[nt][0] * i0, oacc[nt][1] * i0);
        *(float2*)(Og8 + col) = make_float2(oacc[nt][2] * i1, oacc[nt][3] * i1);
    }
}

// ---------------------------------------------------------------------------
// launch
// ---------------------------------------------------------------------------
extern "C" void kernel_launch(void* const* d_in, const int* in_sizes, int n_in,
                              void* d_out, int out_size) {
    const float* x  = (const float*)d_in[0];
    const float* Wq = (const float*)d_in[1];
    const float* Wk = (const float*)d_in[2];
    const float* Wv = (const float*)d_in[3];
    const float* Wo = (const float*)d_in[4];
    const float* qg = (const float*)d_in[5];
    const float* kg = (const float*)d_in[6];
    float* out = (float*)d_out;

    float *pQ, *pK, *pV, *pO;
    cudaGetSymbolAddress((void**)&pQ, g_Q);
    cudaGetSymbolAddress((void**)&pK, g_K);
    cudaGetSymbolAddress((void**)&pV, g_V);
    cudaGetSymbolAddress((void**)&pO, g_O);

    const int M = BATCH * SEQ;  // 4096

    const size_t gsmem = GEMM_SMEM_FLOATS * sizeof(float);
    cudaFuncSetAttribute(gemm_tf32, cudaFuncAttributeMaxDynamicSharedMemorySize, (int)gsmem);

    // QKV projections (tf32 tensor cores)
    gemm_tf32<<<dim3(DMODEL / 128, M / 128), 256, gsmem>>>(M, DMODEL, DMODEL, x, Wq, nullptr, pQ);
    gemm_tf32<<<dim3(KVD    / 128, M / 128), 256, gsmem>>>(M, KVD,    DMODEL, x, Wk, nullptr, pK);
    gemm_tf32<<<dim3(KVD    / 128, M / 128), 256, gsmem>>>(M, KVD,    DMODEL, x, Wv, nullptr, pV);

    // per-head RMSNorm
    rmsnorm128<<<(M * NHEAD) / 8, 256>>>(pQ, qg, M * NHEAD);
    rmsnorm128<<<(M * NKVH)  / 8, 256>>>(pK, kg, M * NKVH);

    // causal GQA flash attention (tf32 tensor cores)
    const size_t fsmem = FA_SMEM_FLOATS * sizeof(float);
    cudaFuncSetAttribute(flash_tf32, cudaFuncAttributeMaxDynamicSharedMemorySize, (int)fsmem);
    flash_tf32<<<dim3(SEQ / 128, NHEAD, BATCH), 256, fsmem>>>(pQ, pK, pV, pO);

    // output projection + residual (tf32 tensor cores)
    gemm_tf32<<<dim3(DMODEL / 128, M / 128), 256, gsmem>>>(M, DMODEL, DMODEL, pO, Wo, x, out);
}

// round 4
// speedup vs baseline: 4.8417x; 1.0076x over previous
#include <cuda_runtime.h>
#include <cuda_bf16.h>
#include <cstdint>

// ---------------------------------------------------------------------------
// Problem constants
// ---------------------------------------------------------------------------
#define BATCH 2
#define SEQ   2048
#define DMODEL 2048
#define KVD    512
#define NHEAD  16
#define NKVH   4
#define DHEAD  128

// Scratch buffers (allocation-free rule: __device__ globals)
__device__ float g_Q[BATCH * SEQ * DMODEL];
__device__ float g_K[BATCH * SEQ * KVD];
__device__ float g_V[BATCH * SEQ * KVD];
__device__ float g_O[BATCH * SEQ * DMODEL];

__device__ __forceinline__ float tf32r(float x) {
    uint32_t u;
    asm("cvt.rna.tf32.f32 %0, %1;" : "=r"(u) : "f"(x));
    return __uint_as_float(u);
}

__device__ __forceinline__ uint32_t packbf2(float lo, float hi) {
    __nv_bfloat162 h = __floats2bfloat162_rn(lo, hi);
    return *reinterpret_cast<uint32_t*>(&h);
}

__device__ __forceinline__ void mma_tf32(float c[4], const float a[4], const float b[2]) {
    asm volatile(
        "mma.sync.aligned.m16n8k8.row.col.f32.tf32.tf32.f32 "
        "{%0,%1,%2,%3}, {%4,%5,%6,%7}, {%8,%9}, {%0,%1,%2,%3};\n"
        : "+f"(c[0]), "+f"(c[1]), "+f"(c[2]), "+f"(c[3])
        : "r"(__float_as_uint(a[0])), "r"(__float_as_uint(a[1])),
          "r"(__float_as_uint(a[2])), "r"(__float_as_uint(a[3])),
          "r"(__float_as_uint(b[0])), "r"(__float_as_uint(b[1])));
}

__device__ __forceinline__ void mma_bf16(float c[4], const uint32_t a[4], const uint32_t b[2]) {
    asm volatile(
        "mma.sync.aligned.m16n8k16.row.col.f32.bf16.bf16.f32 "
        "{%0,%1,%2,%3}, {%4,%5,%6,%7}, {%8,%9}, {%0,%1,%2,%3};\n"
        : "+f"(c[0]), "+f"(c[1]), "+f"(c[2]), "+f"(c[3])
        : "r"(a[0]), "r"(a[1]), "r"(a[2]), "r"(a[3]),
          "r"(b[0]), "r"(b[1]));
}

// ---------------------------------------------------------------------------
// BF16 tensor-core GEMM: C[M,N] = A[M,K] @ B[K,N] (+ optional residual R)
// fp32 in/out, bf16 mma operands, fp32 accumulate.
// 128x128x32 CTA tile, 256 threads (8 warps, 2x4), 64x32 warp tile,
// mma.m16n8k16. Operands packed bf16x2 (along k) in u32 smem:
//   As u32[128][20]  (stride 20:  bank = 20*grp+tig  -> bijective mod 32)
//   Bs u32[16][136]  (kp-major, stride 136: bank = 8*tig+grp -> bijective)
// Double-buffered, register prefetch.
// ---------------------------------------------------------------------------
#define ABF_STRIDE 20
#define BBF_STRIDE 136
#define ABF_SZ (128 * ABF_STRIDE)   // 2560 u32
#define BBF_SZ (16 * BBF_STRIDE)    // 2176 u32
#define GEMM_SMEM_U32 (2 * ABF_SZ + 2 * BBF_SZ)

__global__ __launch_bounds__(256)
void gemm_bf16(int M, int N, int K,
               const float* __restrict__ A,
               const float* __restrict__ B,
               const float* __restrict__ R,
               float* __restrict__ C) {
    extern __shared__ uint32_t smu[];
    uint32_t* As = smu;                 // 2 x [128][20]
    uint32_t* Bs = smu + 2 * ABF_SZ;    // 2 x [16][136]

    const int tid    = threadIdx.x;
    const int lane   = tid & 31;
    const int warpId = tid >> 5;
    const int warpRow = warpId & 1;      // 0..1 (64 rows)
    const int warpCol = warpId >> 1;     // 0..3 (32 cols)
    const int grp = lane >> 2;           // 0..7
    const int tig = lane & 3;            // 0..3

    const float* Ablk = A + (size_t)blockIdx.y * 128 * K;
    const float* Bblk = B + blockIdx.x * 128;

    // staging indices
    const int aRow  = tid >> 1;           // 0..127
    const int aHalf = tid & 1;            // 0..1 -> k cols half*16..+15
    const int bKp   = tid >> 4;           // 0..15 packed-k row
    const int bC    = (tid & 15) * 8;     // 8 cols

    float acc[4][4][4];
    #pragma unroll
    for (int i = 0; i < 4; i++)
        #pragma unroll
        for (int j = 0; j < 4; j++)
            #pragma unroll
            for (int q = 0; q < 4; q++) acc[i][j][q] = 0.f;

    float4 ra[4];   // A: 16 floats = one 16-k half-row
    float4 rb[4];   // B: rows 2kp,2kp+1 x 8 cols

    // ---- prologue: tile 0 ----
    #pragma unroll
    for (int it = 0; it < 4; it++)
        ra[it] = *(const float4*)(Ablk + (size_t)aRow * K + aHalf * 16 + it * 4);
    {
        const float* B0 = Bblk + (size_t)(2 * bKp) * N + bC;
        const float* B1 = B0 + N;
        rb[0] = *(const float4*)(B0);
        rb[1] = *(const float4*)(B0 + 4);
        rb[2] = *(const float4*)(B1);
        rb[3] = *(const float4*)(B1 + 4);
    }
    {
        uint32_t* pa = As + aRow * ABF_STRIDE + aHalf * 8;
        const float* rf = (const float*)ra;
        #pragma unroll
        for (int j = 0; j < 8; j++) pa[j] = packbf2(rf[2 * j], rf[2 * j + 1]);
        uint32_t* pb = Bs + bKp * BBF_STRIDE + bC;
        const float* f0 = (const float*)&rb[0];
        const float* f1 = (const float*)&rb[2];
        #pragma unroll
        for (int j = 0; j < 8; j++) pb[j] = packbf2(f0[j], f1[j]);
    }
    __syncthreads();

    int buf = 0;
    for (int k0 = 0; k0 < K; k0 += 32) {
        const bool more = (k0 + 32) < K;
        if (more) {
            #pragma unroll
            for (int it = 0; it < 4; it++)
                ra[it] = *(const float4*)(Ablk + (size_t)aRow * K + k0 + 32 + aHalf * 16 + it * 4);
            const float* B0 = Bblk + (size_t)(k0 + 32 + 2 * bKp) * N + bC;
            const float* B1 = B0 + N;
            rb[0] = *(const float4*)(B0);
            rb[1] = *(const float4*)(B0 + 4);
            rb[2] = *(const float4*)(B1);
            rb[3] = *(const float4*)(B1 + 4);
        }

        // ---- compute on current buffer: 2 k-steps of 16 ----
        const uint32_t* Ab = As + buf * ABF_SZ;
        const uint32_t* Bb = Bs + buf * BBF_SZ;
        #pragma unroll
        for (int ks = 0; ks < 2; ks++) {
            uint32_t afr[4][4], bfr[4][2];
            #pragma unroll
            for (int mt = 0; mt < 4; mt++) {
                const int rbs = warpRow * 64 + mt * 16 + grp;
                const uint32_t* r0 = Ab + rbs * ABF_STRIDE + ks * 8;
                const uint32_t* r8 = r0 + 8 * ABF_STRIDE;
                afr[mt][0] = r0[tig];
                afr[mt][1] = r8[tig];
                afr[mt][2] = r0[tig + 4];
                afr[mt][3] = r8[tig + 4];
            }
            #pragma unroll
            for (int nt = 0; nt < 4; nt++) {
                const int cb = warpCol * 32 + nt * 8 + grp;
                bfr[nt][0] = Bb[(ks * 8 + tig    ) * BBF_STRIDE + cb];
                bfr[nt][1] = Bb[(ks * 8 + tig + 4) * BBF_STRIDE + cb];
            }
            #pragma unroll
            for (int mt = 0; mt < 4; mt++)
                #pragma unroll
                for (int nt = 0; nt < 4; nt++)
                    mma_bf16(acc[mt][nt], afr[mt], bfr[nt]);
        }

        if (more) {
            const int nb = buf ^ 1;
            uint32_t* pa = As + nb * ABF_SZ + aRow * ABF_STRIDE + aHalf * 8;
            const float* rf = (const float*)ra;
            #pragma unroll
            for (int j = 0; j < 8; j++) pa[j] = packbf2(rf[2 * j], rf[2 * j + 1]);
            uint32_t* pb = Bs + nb * BBF_SZ + bKp * BBF_STRIDE + bC;
            const float* f0 = (const float*)&rb[0];
            const float* f1 = (const float*)&rb[2];
            #pragma unroll
            for (int j = 0; j < 8; j++) pb[j] = packbf2(f0[j], f1[j]);
        }
        __syncthreads();
        buf ^= 1;
    }

    // ---- epilogue ----
    #pragma unroll
    for (int mt = 0; mt < 4; mt++) {
        #pragma unroll
        for (int nt = 0; nt < 4; nt++) {
            const int row = blockIdx.y * 128 + warpRow * 64 + mt * 16 + grp;
            const int col = blockIdx.x * 128 + warpCol * 32 + nt * 8 + 2 * tig;
            float2 v0 = make_float2(acc[mt][nt][0], acc[mt][nt][1]);
            float2 v1 = make_float2(acc[mt][nt][2], acc[mt][nt][3]);
            if (R) {
                const float2 r0 = *(const float2*)(R + (size_t)row * N + col);
                const float2 r1 = *(const float2*)(R + (size_t)(row + 8) * N + col);
                v0.x += r0.x; v0.y += r0.y;
                v1.x += r1.x; v1.y += r1.y;
            }
            *(float2*)(C + (size_t)row * N + col) = v0;
            *(float2*)(C + (size_t)(row + 8) * N + col) = v1;
        }
    }
}

// ---------------------------------------------------------------------------
// RMSNorm over contiguous 128-float vectors: one warp per vector
// ---------------------------------------------------------------------------
__global__ __launch_bounds__(256)
void rmsnorm128(float* __restrict__ t, const float* __restrict__ gamma, int nvec) {
    const int w = (blockIdx.x * blockDim.x + threadIdx.x) >> 5;
    if (w >= nvec) return;
    const int lane = threadIdx.x & 31;
    float4* p = (float4*)(t + (size_t)w * DHEAD) + lane;
    float4 v = *p;
    float ss = v.x * v.x + v.y * v.y + v.z * v.z + v.w * v.w;
    #pragma unroll
    for (int o = 16; o; o >>= 1) ss += __shfl_xor_sync(0xffffffffu, ss, o);
    const float rs = rsqrtf(ss * (1.0f / 128.0f) + 1e-8f);
    const float4 gg = ((const float4*)gamma)[lane];
    v.x *= rs * gg.x; v.y *= rs * gg.y; v.z *= rs * gg.z; v.w *= rs * gg.w;
    *p = v;
}

// ---------------------------------------------------------------------------
// TF32 tensor-core flash attention (causal, GQA) — unchanged from R3
// ---------------------------------------------------------------------------
#define KS_STRIDE 132
#define VS_STRIDE 136
#define FA_SMEM_FLOATS (64 * KS_STRIDE + 64 * VS_STRIDE)

__global__ __launch_bounds__(256, 1)
void flash_tf32(const float* __restrict__ Qb,
                const float* __restrict__ Kb,
                const float* __restrict__ Vb,
                float* __restrict__ Ob) {
    const int qb = blockIdx.x;
    const int h  = blockIdx.y;
    const int b  = blockIdx.z;
    const int kvh = h >> 2;

    extern __shared__ float sm[];
    float* Ks = sm;
    float* Vs = sm + 64 * KS_STRIDE;

    const int tid  = threadIdx.x;
    const int lane = tid & 31;
    const int w    = tid >> 5;
    const int grp  = lane >> 2;
    const int tig  = lane & 3;
    const int q0   = qb * 128;

    const int r0g = q0 + w * 16 + grp;

    const float SCALE = 0.08838834764831845f;
    float qf[16][4];
    {
        const float* Qg  = Qb + ((size_t)(b * SEQ + r0g) * DMODEL) + h * DHEAD;
        const float* Qg8 = Qg + 8 * (size_t)DMODEL;
        #pragma unroll
        for (int kt = 0; kt < 16; kt++) {
            qf[kt][0] = tf32r(Qg [kt * 8 + tig    ] * SCALE);
            qf[kt][1] = tf32r(Qg8[kt * 8 + tig    ] * SCALE);
            qf[kt][2] = tf32r(Qg [kt * 8 + tig + 4] * SCALE);
            qf[kt][3] = tf32r(Qg8[kt * 8 + tig + 4] * SCALE);
        }
    }

    float oacc[16][4];
    #pragma unroll
    for (int i = 0; i < 16; i++)
        #pragma unroll
        for (int q = 0; q < 4; q++) oacc[i][q] = 0.f;
    float m0 = -1e30f, m1 = -1e30f, l0 = 0.f, l1 = 0.f;

    const int ntiles = 2 * qb + 2;

    for (int t = 0; t < ntiles; t++) {
        const int kv0 = t * 64;
        __syncthreads();

        {
            const float* Kg = Kb + ((size_t)(b * SEQ + kv0) * KVD) + kvh * DHEAD;
            const float* Vg = Vb + ((size_t)(b * SEQ + kv0) * KVD) + kvh * DHEAD;
            #pragma unroll
            for (int i = tid; i < 64 * 32; i += 256) {
                const int row = i >> 5, c4 = (i & 31) * 4;
                float4 kx = *(const float4*)(Kg + (size_t)row * KVD + c4);
                kx.x = tf32r(kx.x); kx.y = tf32r(kx.y);
                kx.z = tf32r(kx.z); kx.w = tf32r(kx.w);
                *(float4*)(Ks + row * KS_STRIDE + c4) = kx;
                float4 vx = *(const float4*)(Vg + (size_t)row * KVD + c4);
                vx.x = tf32r(vx.x); vx.y = tf32r(vx.y);
                vx.z = tf32r(vx.z); vx.w = tf32r(vx.w);
                *(float4*)(Vs + row * VS_STRIDE + c4) = vx;
            }
        }
        __syncthreads();

        float s[8][4];
        #pragma unroll
        for (int nt = 0; nt < 8; nt++)
            #pragma unroll
            for (int q = 0; q < 4; q++) s[nt][q] = 0.f;

        #pragma unroll
        for (int kt = 0; kt < 16; kt++) {
            #pragma unroll
            for (int nt = 0; nt < 8; nt++) {
                float bf[2];
                bf[0] = Ks[(nt * 8 + grp) * KS_STRIDE + kt * 8 + tig    ];
                bf[1] = Ks[(nt * 8 + grp) * KS_STRIDE + kt * 8 + tig + 4];
                mma_tf32(s[nt], qf[kt], bf);
            }
        }

        if (t >= 2 * qb) {
            #pragma unroll
            for (int nt = 0; nt < 8; nt++) {
                const int col = kv0 + nt * 8 + 2 * tig;
                if (col     > r0g    ) s[nt][0] = -1e30f;
                if (col + 1 > r0g    ) s[nt][1] = -1e30f;
                if (col     > r0g + 8) s[nt][2] = -1e30f;
                if (col + 1 > r0g + 8) s[nt][3] = -1e30f;
            }
        }

        float mx0 = -1e30f, mx1 = -1e30f;
        #pragma unroll
        for (int nt = 0; nt < 8; nt++) {
            mx0 = fmaxf(mx0, fmaxf(s[nt][0], s[nt][1]));
            mx1 = fmaxf(mx1, fmaxf(s[nt][2], s[nt][3]));
        }
        mx0 = fmaxf(mx0, __shfl_xor_sync(0xffffffffu, mx0, 1));
        mx0 = fmaxf(mx0, __shfl_xor_sync(0xffffffffu, mx0, 2));
        mx1 = fmaxf(mx1, __shfl_xor_sync(0xffffffffu, mx1, 1));
        mx1 = fmaxf(mx1, __shfl_xor_sync(0xffffffffu, mx1, 2));

        const float mn0 = fmaxf(m0, mx0);
        const float mn1 = fmaxf(m1, mx1);
        const float al0 = __expf(m0 - mn0);
        const float al1 = __expf(m1 - mn1);

        float ls0 = 0.f, ls1 = 0.f;
        #pragma unroll
        for (int nt = 0; nt < 8; nt++) {
            s[nt][0] = __expf(s[nt][0] - mn0);
            s[nt][1] = __expf(s[nt][1] - mn0);
            s[nt][2] = __expf(s[nt][2] - mn1);
            s[nt][3] = __expf(s[nt][3] - mn1);
            ls0 += s[nt][0] + s[nt][1];
            ls1 += s[nt][2] + s[nt][3];
        }
        ls0 += __shfl_xor_sync(0xffffffffu, ls0, 1);
        ls0 += __shfl_xor_sync(0xffffffffu, ls0, 2);
        ls1 += __shfl_xor_sync(0xffffffffu, ls1, 1);
        ls1 += __shfl_xor_sync(0xffffffffu, ls1, 2);
        l0 = l0 * al0 + ls0;  m0 = mn0;
        l1 = l1 * al1 + ls1;  m1 = mn1;

        #pragma unroll
        for (int nt = 0; nt < 16; nt++) {
            oacc[nt][0] *= al0; oacc[nt][1] *= al0;
            oacc[nt][2] *= al1; oacc[nt][3] *= al1;
        }

        const int sl0 = (lane & 28) | (tig >> 1);
        const int sl1 = sl0 + 2;
        const bool odd = (tig & 1);
        #pragma unroll
        for (int kt = 0; kt < 8; kt++) {
            float x0 = __shfl_sync(0xffffffffu, s[kt][0], sl0);
            float x1 = __shfl_sync(0xffffffffu, s[kt][1], sl0);
            float x2 = __shfl_sync(0xffffffffu, s[kt][2], sl0);
            float x3 = __shfl_sync(0xffffffffu, s[kt][3], sl0);
            float y0 = __shfl_sync(0xffffffffu, s[kt][0], sl1);
            float y1 = __shfl_sync(0xffffffffu, s[kt][1], sl1);
            float y2 = __shfl_sync(0xffffffffu, s[kt][2], sl1);
            float y3 = __shfl_sync(0xffffffffu, s[kt][3], sl1);
            float af[4];
            af[0] = tf32r(odd ? x1 : x0);
            af[1] = tf32r(odd ? x3 : x2);
            af[2] = tf32r(odd ? y1 : y0);
            af[3] = tf32r(odd ? y3 : y2);
            #pragma unroll
            for (int nt = 0; nt < 16; nt++) {
                float bf[2];
                bf[0] = Vs[(kt * 8 + tig    ) * VS_STRIDE + nt * 8 + grp];
                bf[1] = Vs[(kt * 8 + tig + 4) * VS_STRIDE + nt * 8 + grp];
                mma_tf32(oacc[nt], af, bf);
            }
        }
    }

    const float i0 = 1.0f / l0;
    const float i1 = 1.0f / l1;
    float* Og  = Ob + ((size_t)(b * SEQ + r0g) * DMODEL) + h * DHEAD;
    float* Og8 = Og + 8 * (size_t)DMODEL;
    #pragma unroll
    for (int nt = 0; nt < 16; nt++) {
        const int col = nt * 8 + 2 * tig;
        *(float2*)(Og  + col) = make_float2(oacc[nt][0] * i0, oacc[nt][1] * i0);
        *(float2*)(Og8 + col) = make_float2(oacc[nt][2] * i1, oacc[nt][3] * i1);
    }
}

// ---------------------------------------------------------------------------
// launch
// ---------------------------------------------------------------------------
extern "C" void kernel_launch(void* const* d_in, const int* in_sizes, int n_in,
                              void* d_out, int out_size) {
    const float* x  = (const float*)d_in[0];
    const float* Wq = (const float*)d_in[1];
    const float* Wk = (const float*)d_in[2];
    const float* Wv = (const float*)d_in[3];
    const float* Wo = (const float*)d_in[4];
    const float* qg = (const float*)d_in[5];
    const float* kg = (const float*)d_in[6];
    float* out = (float*)d_out;

    float *pQ, *pK, *pV, *pO;
    cudaGetSymbolAddress((void**)&pQ, g_Q);
    cudaGetSymbolAddress((void**)&pK, g_K);
    cudaGetSymbolAddress((void**)&pV, g_V);
    cudaGetSymbolAddress((void**)&pO, g_O);

    const int M = BATCH * SEQ;  // 4096

    const size_t gsmem = GEMM_SMEM_U32 * sizeof(uint32_t);
    cudaFuncSetAttribute(gemm_bf16, cudaFuncAttributeMaxDynamicSharedMemorySize, (int)gsmem);

    // QKV projections (bf16 tensor cores, fp32 accumulate)
    gemm_bf16<<<dim3(DMODEL / 128, M / 128), 256, gsmem>>>(M, DMODEL, DMODEL, x, Wq, nullptr, pQ);
    gemm_bf16<<<dim3(KVD    / 128, M / 128), 256, gsmem>>>(M, KVD,    DMODEL, x, Wk, nullptr, pK);
    gemm_bf16<<<dim3(KVD    / 128, M / 128), 256, gsmem>>>(M, KVD,    DMODEL, x, Wv, nullptr, pV);

    // per-head RMSNorm
    rmsnorm128<<<(M * NHEAD) / 8, 256>>>(pQ, qg, M * NHEAD);
    rmsnorm128<<<(M * NKVH)  / 8, 256>>>(pK, kg, M * NKVH);

    // causal GQA flash attention (tf32 tensor cores)
    const size_t fsmem = FA_SMEM_FLOATS * sizeof(float);
    cudaFuncSetAttribute(flash_tf32, cudaFuncAttributeMaxDynamicSharedMemorySize, (int)fsmem);
    flash_tf32<<<dim3(SEQ / 128, NHEAD, BATCH), 256, fsmem>>>(pQ, pK, pV, pO);

    // output projection + residual (bf16 tensor cores)
    gemm_bf16<<<dim3(DMODEL / 128, M / 128), 256, gsmem>>>(M, DMODEL, DMODEL, pO, Wo, x, out);
}

// round 5
// speedup vs baseline: 7.3866x; 1.5256x over previous
#include <cuda_runtime.h>
#include <cuda_bf16.h>
#include <cstdint>

// ---------------------------------------------------------------------------
// Problem constants
// ---------------------------------------------------------------------------
#define BATCH 2
#define SEQ   2048
#define DMODEL 2048
#define KVD    512
#define NHEAD  16
#define NKVH   4
#define DHEAD  128

// Scratch buffers (allocation-free rule: __device__ globals)
__device__ float g_Q[BATCH * SEQ * DMODEL];
__device__ float g_K[BATCH * SEQ * KVD];
__device__ float g_V[BATCH * SEQ * KVD];
__device__ __nv_bfloat16 g_xb [BATCH * SEQ * DMODEL];
__device__ __nv_bfloat16 g_Ob [BATCH * SEQ * DMODEL];
__device__ __nv_bfloat16 g_Wqb[DMODEL * DMODEL];
__device__ __nv_bfloat16 g_Wkb[DMODEL * KVD];
__device__ __nv_bfloat16 g_Wvb[DMODEL * KVD];
__device__ __nv_bfloat16 g_Wob[DMODEL * DMODEL];

__device__ __forceinline__ float tf32r(float x) {
    uint32_t u;
    asm("cvt.rna.tf32.f32 %0, %1;" : "=r"(u) : "f"(x));
    return __uint_as_float(u);
}

__device__ __forceinline__ uint32_t packbf2(float lo, float hi) {
    __nv_bfloat162 h = __floats2bfloat162_rn(lo, hi);
    return *reinterpret_cast<uint32_t*>(&h);
}

__device__ __forceinline__ uint32_t smem_u32(const void* p) {
    return (uint32_t)__cvta_generic_to_shared(p);
}

__device__ __forceinline__ void cp16(void* dst, const void* src) {
    asm volatile("cp.async.cg.shared.global [%0], [%1], 16;"
                 :: "r"(smem_u32(dst)), "l"(src));
}
#define CP_COMMIT() asm volatile("cp.async.commit_group;")
#define CP_WAIT1()  asm volatile("cp.async.wait_group 1;")

__device__ __forceinline__ void ldsm_x4(uint32_t r[4], uint32_t addr) {
    asm volatile("ldmatrix.sync.aligned.m8n8.x4.shared.b16 {%0,%1,%2,%3}, [%4];"
                 : "=r"(r[0]), "=r"(r[1]), "=r"(r[2]), "=r"(r[3]) : "r"(addr));
}
__device__ __forceinline__ void ldsm_x4_t(uint32_t r[4], uint32_t addr) {
    asm volatile("ldmatrix.sync.aligned.m8n8.x4.trans.shared.b16 {%0,%1,%2,%3}, [%4];"
                 : "=r"(r[0]), "=r"(r[1]), "=r"(r[2]), "=r"(r[3]) : "r"(addr));
}

__device__ __forceinline__ void mma_tf32(float c[4], const float a[4], const float b[2]) {
    asm volatile(
        "mma.sync.aligned.m16n8k8.row.col.f32.tf32.tf32.f32 "
        "{%0,%1,%2,%3}, {%4,%5,%6,%7}, {%8,%9}, {%0,%1,%2,%3};\n"
        : "+f"(c[0]), "+f"(c[1]), "+f"(c[2]), "+f"(c[3])
        : "r"(__float_as_uint(a[0])), "r"(__float_as_uint(a[1])),
          "r"(__float_as_uint(a[2])), "r"(__float_as_uint(a[3])),
          "r"(__float_as_uint(b[0])), "r"(__float_as_uint(b[1])));
}

__device__ __forceinline__ void mma_bf16(float c[4], const uint32_t a[4], const uint32_t b[2]) {
    asm volatile(
        "mma.sync.aligned.m16n8k16.row.col.f32.bf16.bf16.f32 "
        "{%0,%1,%2,%3}, {%4,%5,%6,%7}, {%8,%9}, {%0,%1,%2,%3};\n"
        : "+f"(c[0]), "+f"(c[1]), "+f"(c[2]), "+f"(c[3])
        : "r"(a[0]), "r"(a[1]), "r"(a[2]), "r"(a[3]),
          "r"(b[0]), "r"(b[1]));
}

// ---------------------------------------------------------------------------
// fp32 -> bf16 conversion (vectorized)
// ---------------------------------------------------------------------------
__global__ __launch_bounds__(256)
void cvt_bf16(const float4* __restrict__ src, uint32_t* __restrict__ dst, int n4) {
    const int i = blockIdx.x * blockDim.x + threadIdx.x;
    if (i >= n4) return;
    const float4 v = src[i];
    dst[2 * i]     = packbf2(v.x, v.y);
    dst[2 * i + 1] = packbf2(v.z, v.w);
}

// ---------------------------------------------------------------------------
// BF16 tensor-core GEMM, cp.async + ldmatrix, 3-stage pipeline.
// C[M,N] fp32 = A[M,K]bf16 @ B[K,N]bf16 (+ optional fp32 residual R)
// CTA 128x128x32, 256 threads (8 warps 2x4), warp tile 64x32, mma.m16n8k16.
// smem: As bf16[128][40] (LDSM 8-row phases: 5r mod 8 bijective),
//       Bs bf16[32][136] (17r mod 8 bijective) -> conflict-free LDSM.
// ---------------------------------------------------------------------------
#define AST 40
#define BST 136
#define A_STG (128 * AST)            // 5120 bf16
#define B_STG (32 * BST)             // 4352 bf16
#define STG_ELEMS (A_STG + B_STG)    // 9472 bf16 = 18944 B
#define GEMM_SMEM_BYTES (3 * STG_ELEMS * 2)

__global__ __launch_bounds__(256)
void gemm_bf16_tc(int M, int N, int K,
                  const __nv_bfloat16* __restrict__ A,
                  const __nv_bfloat16* __restrict__ B,
                  const float* __restrict__ R,
                  float* __restrict__ C) {
    extern __shared__ __nv_bfloat16 smb[];

    const int tid  = threadIdx.x;
    const int lane = tid & 31;
    const int wid  = tid >> 5;
    const int warpRow = wid & 1;      // 0..1 -> 64 rows
    const int warpCol = wid >> 1;     // 0..3 -> 32 cols
    const int grp = lane >> 2;
    const int tig = lane & 3;
    const size_t bm = (size_t)blockIdx.y * 128;
    const size_t bn = (size_t)blockIdx.x * 128;

    // ldmatrix lane addressing
    const int lrow = (lane & 7) + (lane & 8);       // 0..15
    const int lcol8 = ((lane >> 4) << 3);           // 0 or 8

    float acc[4][4][4];
    #pragma unroll
    for (int i = 0; i < 4; i++)
        #pragma unroll
        for (int j = 0; j < 4; j++)
            #pragma unroll
            for (int q = 0; q < 4; q++) acc[i][j][q] = 0.f;

    const int T = K / 32;

    // ---- async stage issue ----
    auto issue = [&](int stage, int k0) {
        __nv_bfloat16* As = smb + stage * STG_ELEMS;
        __nv_bfloat16* Bs = As + A_STG;
        #pragma unroll
        for (int t = 0; t < 2; t++) {
            const int c = tid + t * 256;
            const int ar = c >> 2, akc = (c & 3) * 8;
            cp16(As + ar * AST + akc, A + (bm + ar) * K + k0 + akc);
            const int br = c >> 4, bnc = (c & 15) * 8;
            cp16(Bs + br * BST + bnc, B + (size_t)(k0 + br) * N + bn + bnc);
        }
        CP_COMMIT();
    };

    issue(0, 0);
    issue(1, 32);

    for (int i = 0; i < T; i++) {
        CP_WAIT1();
        __syncthreads();
        if (i + 2 < T) issue((i + 2) % 3, (i + 2) * 32);

        const __nv_bfloat16* As = smb + (i % 3) * STG_ELEMS;
        const __nv_bfloat16* Bs = As + A_STG;
        const uint32_t sA = smem_u32(As);
        const uint32_t sB = smem_u32(Bs);

        #pragma unroll
        for (int ks = 0; ks < 2; ks++) {
            uint32_t afr[4][4];
            #pragma unroll
            for (int mt = 0; mt < 4; mt++) {
                const int r = warpRow * 64 + mt * 16 + lrow;
                ldsm_x4(afr[mt], sA + (uint32_t)(r * AST + ks * 16 + lcol8) * 2);
            }
            uint32_t bfr[4][2];
            #pragma unroll
            for (int half = 0; half < 2; half++) {
                const int brow = ks * 16 + lrow;
                const int ncol = warpCol * 32 + half * 16 + lcol8;
                uint32_t rr[4];
                ldsm_x4_t(rr, sB + (uint32_t)(brow * BST + ncol) * 2);
                bfr[2 * half][0] = rr[0]; bfr[2 * half][1] = rr[1];
                bfr[2 * half + 1][0] = rr[2]; bfr[2 * half + 1][1] = rr[3];
            }
            #pragma unroll
            for (int mt = 0; mt < 4; mt++)
                #pragma unroll
                for (int nt = 0; nt < 4; nt++)
                    mma_bf16(acc[mt][nt], afr[mt], bfr[nt]);
        }
    }

    // ---- epilogue ----
    #pragma unroll
    for (int mt = 0; mt < 4; mt++) {
        #pragma unroll
        for (int nt = 0; nt < 4; nt++) {
            const int row = (int)bm + warpRow * 64 + mt * 16 + grp;
            const int col = (int)bn + warpCol * 32 + nt * 8 + 2 * tig;
            float2 v0 = make_float2(acc[mt][nt][0], acc[mt][nt][1]);
            float2 v1 = make_float2(acc[mt][nt][2], acc[mt][nt][3]);
            if (R) {
                const float2 r0 = *(const float2*)(R + (size_t)row * N + col);
                const float2 r1 = *(const float2*)(R + (size_t)(row + 8) * N + col);
                v0.x += r0.x; v0.y += r0.y;
                v1.x += r1.x; v1.y += r1.y;
            }
            *(float2*)(C + (size_t)row * N + col) = v0;
            *(float2*)(C + (size_t)(row + 8) * N + col) = v1;
        }
    }
}

// ---------------------------------------------------------------------------
// RMSNorm over contiguous 128-float vectors: one warp per vector
// ---------------------------------------------------------------------------
__global__ __launch_bounds__(256)
void rmsnorm128(float* __restrict__ t, const float* __restrict__ gamma, int nvec) {
    const int w = (blockIdx.x * blockDim.x + threadIdx.x) >> 5;
    if (w >= nvec) return;
    const int lane = threadIdx.x & 31;
    float4* p = (float4*)(t + (size_t)w * DHEAD) + lane;
    float4 v = *p;
    float ss = v.x * v.x + v.y * v.y + v.z * v.z + v.w * v.w;
    #pragma unroll
    for (int o = 16; o; o >>= 1) ss += __shfl_xor_sync(0xffffffffu, ss, o);
    const float rs = rsqrtf(ss * (1.0f / 128.0f) + 1e-8f);
    const float4 gg = ((const float4*)gamma)[lane];
    v.x *= rs * gg.x; v.y *= rs * gg.y; v.z *= rs * gg.z; v.w *= rs * gg.w;
    *p = v;
}

// ---------------------------------------------------------------------------
// TF32 tensor-core flash attention (causal, GQA) — output written as bf16
// ---------------------------------------------------------------------------
#define KS_STRIDE 132
#define VS_STRIDE 136
#define FA_SMEM_FLOATS (64 * KS_STRIDE + 64 * VS_STRIDE)

__global__ __launch_bounds__(256, 1)
void flash_tf32(const float* __restrict__ Qb,
                const float* __restrict__ Kb,
                const float* __restrict__ Vb,
                __nv_bfloat16* __restrict__ Ob) {
    const int qb = blockIdx.x;
    const int h  = blockIdx.y;
    const int b  = blockIdx.z;
    const int kvh = h >> 2;

    extern __shared__ float sm[];
    float* Ks = sm;
    float* Vs = sm + 64 * KS_STRIDE;

    const int tid  = threadIdx.x;
    const int lane = tid & 31;
    const int w    = tid >> 5;
    const int grp  = lane >> 2;
    const int tig  = lane & 3;
    const int q0   = qb * 128;

    const int r0g = q0 + w * 16 + grp;

    const float SCALE = 0.08838834764831845f;
    float qf[16][4];
    {
        const float* Qg  = Qb + ((size_t)(b * SEQ + r0g) * DMODEL) + h * DHEAD;
        const float* Qg8 = Qg + 8 * (size_t)DMODEL;
        #pragma unroll
        for (int kt = 0; kt < 16; kt++) {
            qf[kt][0] = tf32r(Qg [kt * 8 + tig    ] * SCALE);
            qf[kt][1] = tf32r(Qg8[kt * 8 + tig    ] * SCALE);
            qf[kt][2] = tf32r(Qg [kt * 8 + tig + 4] * SCALE);
            qf[kt][3] = tf32r(Qg8[kt * 8 + tig + 4] * SCALE);
        }
    }

    float oacc[16][4];
    #pragma unroll
    for (int i = 0; i < 16; i++)
        #pragma unroll
        for (int q = 0; q < 4; q++) oacc[i][q] = 0.f;
    float m0 = -1e30f, m1 = -1e30f, l0 = 0.f, l1 = 0.f;

    const int ntiles = 2 * qb + 2;

    for (int t = 0; t < ntiles; t++) {
        const int kv0 = t * 64;
        __syncthreads();

        {
            const float* Kg = Kb + ((size_t)(b * SEQ + kv0) * KVD) + kvh * DHEAD;
            const float* Vg = Vb + ((size_t)(b * SEQ + kv0) * KVD) + kvh * DHEAD;
            #pragma unroll
            for (int i = tid; i < 64 * 32; i += 256) {
                const int row = i >> 5, c4 = (i & 31) * 4;
                float4 kx = *(const float4*)(Kg + (size_t)row * KVD + c4);
                kx.x = tf32r(kx.x); kx.y = tf32r(kx.y);
                kx.z = tf32r(kx.z); kx.w = tf32r(kx.w);
                *(float4*)(Ks + row * KS_STRIDE + c4) = kx;
                float4 vx = *(const float4*)(Vg + (size_t)row * KVD + c4);
                vx.x = tf32r(vx.x); vx.y = tf32r(vx.y);
                vx.z = tf32r(vx.z); vx.w = tf32r(vx.w);
                *(float4*)(Vs + row * VS_STRIDE + c4) = vx;
            }
        }
        __syncthreads();

        float s[8][4];
        #pragma unroll
        for (int nt = 0; nt < 8; nt++)
            #pragma unroll
            for (int q = 0; q < 4; q++) s[nt][q] = 0.f;

        #pragma unroll
        for (int kt = 0; kt < 16; kt++) {
            #pragma unroll
            for (int nt = 0; nt < 8; nt++) {
                float bf[2];
                bf[0] = Ks[(nt * 8 + grp) * KS_STRIDE + kt * 8 + tig    ];
                bf[1] = Ks[(nt * 8 + grp) * KS_STRIDE + kt * 8 + tig + 4];
                mma_tf32(s[nt], qf[kt], bf);
            }
        }

        if (t >= 2 * qb) {
            #pragma unroll
            for (int nt = 0; nt < 8; nt++) {
                const int col = kv0 + nt * 8 + 2 * tig;
                if (col     > r0g    ) s[nt][0] = -1e30f;
                if (col + 1 > r0g    ) s[nt][1] = -1e30f;
                if (col     > r0g + 8) s[nt][2] = -1e30f;
                if (col + 1 > r0g + 8) s[nt][3] = -1e30f;
            }
        }

        float mx0 = -1e30f, mx1 = -1e30f;
        #pragma unroll
        for (int nt = 0; nt < 8; nt++) {
            mx0 = fmaxf(mx0, fmaxf(s[nt][0], s[nt][1]));
            mx1 = fmaxf(mx1, fmaxf(s[nt][2], s[nt][3]));
        }
        mx0 = fmaxf(mx0, __shfl_xor_sync(0xffffffffu, mx0, 1));
        mx0 = fmaxf(mx0, __shfl_xor_sync(0xffffffffu, mx0, 2));
        mx1 = fmaxf(mx1, __shfl_xor_sync(0xffffffffu, mx1, 1));
        mx1 = fmaxf(mx1, __shfl_xor_sync(0xffffffffu, mx1, 2));

        const float mn0 = fmaxf(m0, mx0);
        const float mn1 = fmaxf(m1, mx1);
        const float al0 = __expf(m0 - mn0);
        const float al1 = __expf(m1 - mn1);

        float ls0 = 0.f, ls1 = 0.f;
        #pragma unroll
        for (int nt = 0; nt < 8; nt++) {
            s[nt][0] = __expf(s[nt][0] - mn0);
            s[nt][1] = __expf(s[nt][1] - mn0);
            s[nt][2] = __expf(s[nt][2] - mn1);
            s[nt][3] = __expf(s[nt][3] - mn1);
            ls0 += s[nt][0] + s[nt][1];
            ls1 += s[nt][2] + s[nt][3];
        }
        ls0 += __shfl_xor_sync(0xffffffffu, ls0, 1);
        ls0 += __shfl_xor_sync(0xffffffffu, ls0, 2);
        ls1 += __shfl_xor_sync(0xffffffffu, ls1, 1);
        ls1 += __shfl_xor_sync(0xffffffffu, ls1, 2);
        l0 = l0 * al0 + ls0;  m0 = mn0;
        l1 = l1 * al1 + ls1;  m1 = mn1;

        #pragma unroll
        for (int nt = 0; nt < 16; nt++) {
            oacc[nt][0] *= al0; oacc[nt][1] *= al0;
            oacc[nt][2] *= al1; oacc[nt][3] *= al1;
        }

        const int sl0 = (lane & 28) | (tig >> 1);
        const int sl1 = sl0 + 2;
        const bool odd = (tig & 1);
        #pragma unroll
        for (int kt = 0; kt < 8; kt++) {
            float x0 = __shfl_sync(0xffffffffu, s[kt][0], sl0);
            float x1 = __shfl_sync(0xffffffffu, s[kt][1], sl0);
            float x2 = __shfl_sync(0xffffffffu, s[kt][2], sl0);
            float x3 = __shfl_sync(0xffffffffu, s[kt][3], sl0);
            float y0 = __shfl_sync(0xffffffffu, s[kt][0], sl1);
            float y1 = __shfl_sync(0xffffffffu, s[kt][1], sl1);
            float y2 = __shfl_sync(0xffffffffu, s[kt][2], sl1);
            float y3 = __shfl_sync(0xffffffffu, s[kt][3], sl1);
            float af[4];
            af[0] = tf32r(odd ? x1 : x0);
            af[1] = tf32r(odd ? x3 : x2);
            af[2] = tf32r(odd ? y1 : y0);
            af[3] = tf32r(odd ? y3 : y2);
            #pragma unroll
            for (int nt = 0; nt < 16; nt++) {
                float bf[2];
                bf[0] = Vs[(kt * 8 + tig    ) * VS_STRIDE + nt * 8 + grp];
                bf[1] = Vs[(kt * 8 + tig + 4) * VS_STRIDE + nt * 8 + grp];
                mma_tf32(oacc[nt], af, bf);
            }
        }
    }

    // --- epilogue: normalize, write bf16 O ---
    const float i0 = 1.0f / l0;
    const float i1 = 1.0f / l1;
    __nv_bfloat16* Og  = Ob + ((size_t)(b * SEQ + r0g) * DMODEL) + h * DHEAD;
    __nv_bfloat16* Og8 = Og + 8 * (size_t)DMODEL;
    #pragma unroll
    for (int nt = 0; nt < 16; nt++) {
        const int col = nt * 8 + 2 * tig;
        *(uint32_t*)(Og  + col) = packbf2(oacc[nt][0] * i0, oacc[nt][1] * i0);
        *(uint32_t*)(Og8 + col) = packbf2(oacc[nt][2] * i1, oacc[nt][3] * i1);
    }
}

// ---------------------------------------------------------------------------
// launch
// ---------------------------------------------------------------------------
extern "C" void kernel_launch(void* const* d_in, const int* in_sizes, int n_in,
                              void* d_out, int out_size) {
    const float* x  = (const float*)d_in[0];
    const float* Wq = (const float*)d_in[1];
    const float* Wk = (const float*)d_in[2];
    const float* Wv = (const float*)d_in[3];
    const float* Wo = (const float*)d_in[4];
    const float* qg = (const float*)d_in[5];
    const float* kg = (const float*)d_in[6];
    float* out = (float*)d_out;

    float *pQ, *pK, *pV;
    __nv_bfloat16 *pxb, *pOb, *pWqb, *pWkb, *pWvb, *pWob;
    cudaGetSymbolAddress((void**)&pQ,  g_Q);
    cudaGetSymbolAddress((void**)&pK,  g_K);
    cudaGetSymbolAddress((void**)&pV,  g_V);
    cudaGetSymbolAddress((void**)&pxb, g_xb);
    cudaGetSymbolAddress((void**)&pOb, g_Ob);
    cudaGetSymbolAddress((void**)&pWqb, g_Wqb);
    cudaGetSymbolAddress((void**)&pWkb, g_Wkb);
    cudaGetSymbolAddress((void**)&pWvb, g_Wvb);
    cudaGetSymbolAddress((void**)&pWob, g_Wob);

    const int M = BATCH * SEQ;  // 4096

    // ---- fp32 -> bf16 conversions ----
    {
        const int nx = M * DMODEL / 4;           // 2M float4
        cvt_bf16<<<(nx + 255) / 256, 256>>>((const float4*)x,  (uint32_t*)pxb,  nx);
        const int nq = DMODEL * DMODEL / 4;
        cvt_bf16<<<(nq + 255) / 256, 256>>>((const float4*)Wq, (uint32_t*)pWqb, nq);
        const int nk = DMODEL * KVD / 4;
        cvt_bf16<<<(nk + 255) / 256, 256>>>((const float4*)Wk, (uint32_t*)pWkb, nk);
        cvt_bf16<<<(nk + 255) / 256, 256>>>((const float4*)Wv, (uint32_t*)pWvb, nk);
        cvt_bf16<<<(nq + 255) / 256, 256>>>((const float4*)Wo, (uint32_t*)pWob, nq);
    }

    cudaFuncSetAttribute(gemm_bf16_tc, cudaFuncAttributeMaxDynamicSharedMemorySize,
                         GEMM_SMEM_BYTES);

    // QKV projections
    gemm_bf16_tc<<<dim3(DMODEL / 128, M / 128), 256, GEMM_SMEM_BYTES>>>(
        M, DMODEL, DMODEL, pxb, pWqb, nullptr, pQ);
    gemm_bf16_tc<<<dim3(KVD / 128, M / 128), 256, GEMM_SMEM_BYTES>>>(
        M, KVD, DMODEL, pxb, pWkb, nullptr, pK);
    gemm_bf16_tc<<<dim3(KVD / 128, M / 128), 256, GEMM_SMEM_BYTES>>>(
        M, KVD, DMODEL, pxb, pWvb, nullptr, pV);

    // per-head RMSNorm
    rmsnorm128<<<(M * NHEAD) / 8, 256>>>(pQ, qg, M * NHEAD);
    rmsnorm128<<<(M * NKVH)  / 8, 256>>>(pK, kg, M * NKVH);

    // causal GQA flash attention (tf32), writes bf16 O
    const size_t fsmem = FA_SMEM_FLOATS * sizeof(float);
    cudaFuncSetAttribute(flash_tf32, cudaFuncAttributeMaxDynamicSharedMemorySize, (int)fsmem);
    flash_tf32<<<dim3(SEQ / 128, NHEAD, BATCH), 256, fsmem>>>(pQ, pK, pV, pOb);

    // output projection + residual
    gemm_bf16_tc<<<dim3(DMODEL / 128, M / 128), 256, GEMM_SMEM_BYTES>>>(
        M, DMODEL, DMODEL, pOb, pWob, x, out);
}

// round 7
// speedup vs baseline: 9.2526x; 1.2526x over previous
#include <cuda_runtime.h>
#include <cuda_bf16.h>
#include <cstdint>

// ---------------------------------------------------------------------------
// Problem constants
// ---------------------------------------------------------------------------
#define BATCH 2
#define SEQ   2048
#define DMODEL 2048
#define KVD    512
#define NHEAD  16
#define NKVH   4
#define DHEAD  128

// Scratch buffers (allocation-free rule: __device__ globals)
__device__ float g_Q[BATCH * SEQ * DMODEL];
__device__ float g_K[BATCH * SEQ * KVD];
__device__ float g_V[BATCH * SEQ * KVD];
__device__ __nv_bfloat16 g_xb [BATCH * SEQ * DMODEL];
__device__ __nv_bfloat16 g_Ob [BATCH * SEQ * DMODEL];
__device__ __nv_bfloat16 g_Wqb[DMODEL * DMODEL];
__device__ __nv_bfloat16 g_Wkb[DMODEL * KVD];
__device__ __nv_bfloat16 g_Wvb[DMODEL * KVD];
__device__ __nv_bfloat16 g_Wob[DMODEL * DMODEL];

__device__ __forceinline__ uint32_t packbf2(float lo, float hi) {
    __nv_bfloat162 h = __floats2bfloat162_rn(lo, hi);
    return *reinterpret_cast<uint32_t*>(&h);
}
__device__ __forceinline__ uint32_t smem_u32(const void* p) {
    return (uint32_t)__cvta_generic_to_shared(p);
}
__device__ __forceinline__ void cp16(void* dst, const void* src) {
    asm volatile("cp.async.cg.shared.global [%0], [%1], 16;"
                 :: "r"(smem_u32(dst)), "l"(src));
}
#define CP_COMMIT() asm volatile("cp.async.commit_group;")
#define CP_WAIT1()  asm volatile("cp.async.wait_group 1;")

__device__ __forceinline__ void ldsm_x4(uint32_t r[4], uint32_t addr) {
    asm volatile("ldmatrix.sync.aligned.m8n8.x4.shared.b16 {%0,%1,%2,%3}, [%4];"
                 : "=r"(r[0]), "=r"(r[1]), "=r"(r[2]), "=r"(r[3]) : "r"(addr));
}
__device__ __forceinline__ void ldsm_x4_t(uint32_t r[4], uint32_t addr) {
    asm volatile("ldmatrix.sync.aligned.m8n8.x4.trans.shared.b16 {%0,%1,%2,%3}, [%4];"
                 : "=r"(r[0]), "=r"(r[1]), "=r"(r[2]), "=r"(r[3]) : "r"(addr));
}

__device__ __forceinline__ void mma_bf16(float c[4], const uint32_t a[4], const uint32_t b[2]) {
    asm volatile(
        "mma.sync.aligned.m16n8k16.row.col.f32.bf16.bf16.f32 "
        "{%0,%1,%2,%3}, {%4,%5,%6,%7}, {%8,%9}, {%0,%1,%2,%3};\n"
        : "+f"(c[0]), "+f"(c[1]), "+f"(c[2]), "+f"(c[3])
        : "r"(a[0]), "r"(a[1]), "r"(a[2]), "r"(a[3]),
          "r"(b[0]), "r"(b[1]));
}

// ---------------------------------------------------------------------------
// fp32 -> bf16 conversion (vectorized)
// ---------------------------------------------------------------------------
__global__ __launch_bounds__(256)
void cvt_bf16(const float4* __restrict__ src, uint32_t* __restrict__ dst, int n4) {
    const int i = blockIdx.x * blockDim.x + threadIdx.x;
    if (i >= n4) return;
    const float4 v = src[i];
    dst[2 * i]     = packbf2(v.x, v.y);
    dst[2 * i + 1] = packbf2(v.z, v.w);
}

// ---------------------------------------------------------------------------
// BF16 tensor-core GEMM, cp.async + ldmatrix, 3-stage pipeline (R5, passing).
// ---------------------------------------------------------------------------
#define AST 40
#define BST 136
#define A_STG (128 * AST)
#define B_STG (32 * BST)
#define STG_ELEMS (A_STG + B_STG)
#define GEMM_SMEM_BYTES (3 * STG_ELEMS * 2)

__global__ __launch_bounds__(256)
void gemm_bf16_tc(int M, int N, int K,
                  const __nv_bfloat16* __restrict__ A,
                  const __nv_bfloat16* __restrict__ B,
                  const float* __restrict__ R,
                  float* __restrict__ C) {
    extern __shared__ __nv_bfloat16 smb[];

    const int tid  = threadIdx.x;
    const int lane = tid & 31;
    const int wid  = tid >> 5;
    const int warpRow = wid & 1;
    const int warpCol = wid >> 1;
    const int grp = lane >> 2;
    const int tig = lane & 3;
    const size_t bm = (size_t)blockIdx.y * 128;
    const size_t bn = (size_t)blockIdx.x * 128;

    const int lrow = (lane & 7) + (lane & 8);
    const int lcol8 = ((lane >> 4) << 3);

    float acc[4][4][4];
    #pragma unroll
    for (int i = 0; i < 4; i++)
        #pragma unroll
        for (int j = 0; j < 4; j++)
            #pragma unroll
            for (int q = 0; q < 4; q++) acc[i][j][q] = 0.f;

    const int T = K / 32;

    auto issue = [&](int stage, int k0) {
        __nv_bfloat16* As = smb + stage * STG_ELEMS;
        __nv_bfloat16* Bs = As + A_STG;
        #pragma unroll
        for (int t = 0; t < 2; t++) {
            const int c = tid + t * 256;
            const int ar = c >> 2, akc = (c & 3) * 8;
            cp16(As + ar * AST + akc, A + (bm + ar) * K + k0 + akc);
            const int br = c >> 4, bnc = (c & 15) * 8;
            cp16(Bs + br * BST + bnc, B + (size_t)(k0 + br) * N + bn + bnc);
        }
        CP_COMMIT();
    };

    issue(0, 0);
    issue(1, 32);

    for (int i = 0; i < T; i++) {
        CP_WAIT1();
        __syncthreads();
        if (i + 2 < T) issue((i + 2) % 3, (i + 2) * 32);

        const __nv_bfloat16* As = smb + (i % 3) * STG_ELEMS;
        const __nv_bfloat16* Bs = As + A_STG;
        const uint32_t sA = smem_u32(As);
        const uint32_t sB = smem_u32(Bs);

        #pragma unroll
        for (int ks = 0; ks < 2; ks++) {
            uint32_t afr[4][4];
            #pragma unroll
            for (int mt = 0; mt < 4; mt++) {
                const int r = warpRow * 64 + mt * 16 + lrow;
                ldsm_x4(afr[mt], sA + (uint32_t)(r * AST + ks * 16 + lcol8) * 2);
            }
            uint32_t bfr[4][2];
            #pragma unroll
            for (int half = 0; half < 2; half++) {
                const int brow = ks * 16 + lrow;
                const int ncol = warpCol * 32 + half * 16 + lcol8;
                uint32_t rr[4];
                ldsm_x4_t(rr, sB + (uint32_t)(brow * BST + ncol) * 2);
                bfr[2 * half][0] = rr[0]; bfr[2 * half][1] = rr[1];
                bfr[2 * half + 1][0] = rr[2]; bfr[2 * half + 1][1] = rr[3];
            }
            #pragma unroll
            for (int mt = 0; mt < 4; mt++)
                #pragma unroll
                for (int nt = 0; nt < 4; nt++)
                    mma_bf16(acc[mt][nt], afr[mt], bfr[nt]);
        }
    }

    #pragma unroll
    for (int mt = 0; mt < 4; mt++) {
        #pragma unroll
        for (int nt = 0; nt < 4; nt++) {
            const int row = (int)bm + warpRow * 64 + mt * 16 + grp;
            const int col = (int)bn + warpCol * 32 + nt * 8 + 2 * tig;
            float2 v0 = make_float2(acc[mt][nt][0], acc[mt][nt][1]);
            float2 v1 = make_float2(acc[mt][nt][2], acc[mt][nt][3]);
            if (R) {
                const float2 r0 = *(const float2*)(R + (size_t)row * N + col);
                const float2 r1 = *(const float2*)(R + (size_t)(row + 8) * N + col);
                v0.x += r0.x; v0.y += r0.y;
                v1.x += r1.x; v1.y += r1.y;
            }
            *(float2*)(C + (size_t)row * N + col) = v0;
            *(float2*)(C + (size_t)(row + 8) * N + col) = v1;
        }
    }
}

// ---------------------------------------------------------------------------
// RMSNorm over contiguous 128-float vectors: one warp per vector
// ---------------------------------------------------------------------------
__global__ __launch_bounds__(256)
void rmsnorm128(float* __restrict__ t, const float* __restrict__ gamma, int nvec) {
    const int w = (blockIdx.x * blockDim.x + threadIdx.x) >> 5;
    if (w >= nvec) return;
    const int lane = threadIdx.x & 31;
    float4* p = (float4*)(t + (size_t)w * DHEAD) + lane;
    float4 v = *p;
    float ss = v.x * v.x + v.y * v.y + v.z * v.z + v.w * v.w;
    #pragma unroll
    for (int o = 16; o; o >>= 1) ss += __shfl_xor_sync(0xffffffffu, ss, o);
    const float rs = rsqrtf(ss * (1.0f / 128.0f) + 1e-8f);
    const float4 gg = ((const float4*)gamma)[lane];
    v.x *= rs * gg.x; v.y *= rs * gg.y; v.z *= rs * gg.z; v.w *= rs * gg.w;
    *p = v;
}

// ---------------------------------------------------------------------------
// BF16 tensor-core flash attention (causal, GQA).
// BQ=128 (8 warps x 16 rows), BKV=64, mma.m16n8k16 for both QK^T and PV.
// Q in registers as packed bf16 A-fragments (32 u32). K smem packed along d
// (u32 pairs, stride 68), V smem packed along kv (u32 pairs, stride 136);
// both fragment read patterns bank-conflict-free.
// P accumulator cols (2tig,2tig+1) == bf16 A-fragment k ownership -> the
// P relayout is 4 register packs, no shuffles.
// Heavy q-tiles run first (reversed blockIdx.x) for causal load balance.
// ---------------------------------------------------------------------------
#define KSU_STRIDE 68    // u32: 64 d-pairs + pad
#define VSU_STRIDE 136   // u32: 128 d cols + pad
#define FA_SMEM_U32 (64 * KSU_STRIDE + 32 * VSU_STRIDE)

__global__ __launch_bounds__(256, 1)
void flash_bf16(const float* __restrict__ Qb,
                const float* __restrict__ Kb,
                const float* __restrict__ Vb,
                __nv_bfloat16* __restrict__ Ob) {
    const int qb = gridDim.x - 1 - (int)blockIdx.x;   // heavy tiles first
    const int h  = blockIdx.y;
    const int b  = blockIdx.z;
    const int kvh = h >> 2;

    extern __shared__ uint32_t smu[];
    uint32_t* Ksu = smu;                      // [64 kv][68]  d-pairs
    uint32_t* Vsu = smu + 64 * KSU_STRIDE;    // [32 kv-pairs][136] d cols

    const int tid  = threadIdx.x;
    const int lane = tid & 31;
    const int w    = tid >> 5;                // warp -> q rows [w*16, w*16+16)
    const int grp  = lane >> 2;               // 0..7
    const int tig  = lane & 3;                // 0..3
    const int q0   = qb * 128;

    const int r0g = q0 + w * 16 + grp;        // global q rows r0g, r0g+8

    // --- Q fragments: 8 k-chunks of 16, packed bf16 (pre-scaled) ---
    const float SCALE = 0.08838834764831845f;   // DH^-0.5
    uint32_t qf[8][4];
    {
        const float2* Qg  = (const float2*)(Qb + ((size_t)(b * SEQ + r0g) * DMODEL) + h * DHEAD);
        const float2* Qg8 = (const float2*)((const float*)Qg + 8 * (size_t)DMODEL);
        #pragma unroll
        for (int kt = 0; kt < 8; kt++) {
            const float2 p0 = Qg [kt * 8 + tig];          // d = kt*16 + 2tig
            const float2 p1 = Qg8[kt * 8 + tig];
            const float2 p2 = Qg [kt * 8 + tig + 4];      // d = kt*16 + 8 + 2tig
            const float2 p3 = Qg8[kt * 8 + tig + 4];
            qf[kt][0] = packbf2(p0.x * SCALE, p0.y * SCALE);
            qf[kt][1] = packbf2(p1.x * SCALE, p1.y * SCALE);
            qf[kt][2] = packbf2(p2.x * SCALE, p2.y * SCALE);
            qf[kt][3] = packbf2(p3.x * SCALE, p3.y * SCALE);
        }
    }

    float oacc[16][4];
    #pragma unroll
    for (int i = 0; i < 16; i++)
        #pragma unroll
        for (int q = 0; q < 4; q++) oacc[i][q] = 0.f;
    float m0 = -1e30f, m1 = -1e30f, l0 = 0.f, l1 = 0.f;

    const int ntiles = 2 * qb + 2;            // kv tiles of 64 covering [0, q0+128)

    for (int t = 0; t < ntiles; t++) {
        const int kv0 = t * 64;
        __syncthreads();   // previous iteration's smem reads complete

        // --- stage K (d-pair packed) and V (kv-pair packed) as bf16 ---
        {
            const float* Kg = Kb + ((size_t)(b * SEQ + kv0) * KVD) + kvh * DHEAD;
            #pragma unroll
            for (int i = tid; i < 64 * 32; i += 256) {
                const int row = i >> 5, q4 = i & 31;      // d = q4*4
                const float4 kx = *(const float4*)(Kg + (size_t)row * KVD + q4 * 4);
                Ksu[row * KSU_STRIDE + 2 * q4]     = packbf2(kx.x, kx.y);
                Ksu[row * KSU_STRIDE + 2 * q4 + 1] = packbf2(kx.z, kx.w);
            }
            const float* Vg = Vb + ((size_t)(b * SEQ + kv0) * KVD) + kvh * DHEAD;
            #pragma unroll
            for (int i = tid; i < 32 * 32; i += 256) {
                const int p = i >> 5, q4 = (i & 31) * 4;  // kv rows 2p,2p+1
                const float4 v0 = *(const float4*)(Vg + (size_t)(2 * p) * KVD + q4);
                const float4 v1 = *(const float4*)(Vg + (size_t)(2 * p + 1) * KVD + q4);
                uint32_t* dst = Vsu + p * VSU_STRIDE + q4;
                dst[0] = packbf2(v0.x, v1.x);
                dst[1] = packbf2(v0.y, v1.y);
                dst[2] = packbf2(v0.z, v1.z);
                dst[3] = packbf2(v0.w, v1.w);
            }
        }
        __syncthreads();

        // --- S = Q K^T : 8 n-tiles (64 kv cols), 8 k-chunks of 16 ---
        float s[8][4];
        #pragma unroll
        for (int nt = 0; nt < 8; nt++)
            #pragma unroll
            for (int q = 0; q < 4; q++) s[nt][q] = 0.f;

        #pragma unroll
        for (int kt = 0; kt < 8; kt++) {
            #pragma unroll
            for (int nt = 0; nt < 8; nt++) {
                uint32_t bf[2];
                const uint32_t* kr = Ksu + (nt * 8 + grp) * KSU_STRIDE + kt * 8;
                bf[0] = kr[tig];
                bf[1] = kr[tig + 4];
                mma_bf16(s[nt], qf[kt], bf);
            }
        }

        // --- causal mask (only possibly-masked tiles) ---
        if (t >= 2 * qb) {
            #pragma unroll
            for (int nt = 0; nt < 8; nt++) {
                const int col = kv0 + nt * 8 + 2 * tig;
                if (col     > r0g    ) s[nt][0] = -1e30f;
                if (col + 1 > r0g    ) s[nt][1] = -1e30f;
                if (col     > r0g + 8) s[nt][2] = -1e30f;
                if (col + 1 > r0g + 8) s[nt][3] = -1e30f;
            }
        }

        // --- online softmax (rows r0g, r0g+8; quad holds a row's 64 cols) ---
        float mx0 = -1e30f, mx1 = -1e30f;
        #pragma unroll
        for (int nt = 0; nt < 8; nt++) {
            mx0 = fmaxf(mx0, fmaxf(s[nt][0], s[nt][1]));
            mx1 = fmaxf(mx1, fmaxf(s[nt][2], s[nt][3]));
        }
        mx0 = fmaxf(mx0, __shfl_xor_sync(0xffffffffu, mx0, 1));
        mx0 = fmaxf(mx0, __shfl_xor_sync(0xffffffffu, mx0, 2));
        mx1 = fmaxf(mx1, __shfl_xor_sync(0xffffffffu, mx1, 1));
        mx1 = fmaxf(mx1, __shfl_xor_sync(0xffffffffu, mx1, 2));

        const float mn0 = fmaxf(m0, mx0);
        const float mn1 = fmaxf(m1, mx1);
        const float al0 = __expf(m0 - mn0);
        const float al1 = __expf(m1 - mn1);

        float ls0 = 0.f, ls1 = 0.f;
        #pragma unroll
        for (int nt = 0; nt < 8; nt++) {
            s[nt][0] = __expf(s[nt][0] - mn0);
            s[nt][1] = __expf(s[nt][1] - mn0);
            s[nt][2] = __expf(s[nt][2] - mn1);
            s[nt][3] = __expf(s[nt][3] - mn1);
            ls0 += s[nt][0] + s[nt][1];
            ls1 += s[nt][2] + s[nt][3];
        }
        ls0 += __shfl_xor_sync(0xffffffffu, ls0, 1);
        ls0 += __shfl_xor_sync(0xffffffffu, ls0, 2);
        ls1 += __shfl_xor_sync(0xffffffffu, ls1, 1);
        ls1 += __shfl_xor_sync(0xffffffffu, ls1, 2);
        l0 = l0 * al0 + ls0;  m0 = mn0;
        l1 = l1 * al1 + ls1;  m1 = mn1;

        // rescale running output
        #pragma unroll
        for (int nt = 0; nt < 16; nt++) {
            oacc[nt][0] *= al0; oacc[nt][1] *= al0;
            oacc[nt][2] *= al1; oacc[nt][3] *= al1;
        }

        // --- O += P V : P accumulator packs directly into A fragments ---
        #pragma unroll
        for (int kc = 0; kc < 4; kc++) {
            uint32_t af[4];
            af[0] = packbf2(s[2 * kc][0],     s[2 * kc][1]);       // row grp,  kv 2tig..
            af[1] = packbf2(s[2 * kc][2],     s[2 * kc][3]);       // row grp+8
            af[2] = packbf2(s[2 * kc + 1][0], s[2 * kc + 1][1]);   // row grp,  kv +8
            af[3] = packbf2(s[2 * kc + 1][2], s[2 * kc + 1][3]);   // row grp+8
            #pragma unroll
            for (int nt = 0; nt < 16; nt++) {
                uint32_t bf[2];
                bf[0] = Vsu[(kc * 8 + tig    ) * VSU_STRIDE + nt * 8 + grp];
                bf[1] = Vsu[(kc * 8 + tig + 4) * VSU_STRIDE + nt * 8 + grp];
                mma_bf16(oacc[nt], af, bf);
            }
        }
    }

    // --- epilogue: normalize, write bf16 O ---
    const float i0 = 1.0f / l0;
    const float i1 = 1.0f / l1;
    __nv_bfloat16* Og  = Ob + ((size_t)(b * SEQ + r0g) * DMODEL) + h * DHEAD;
    __nv_bfloat16* Og8 = Og + 8 * (size_t)DMODEL;
    #pragma unroll
    for (int nt = 0; nt < 16; nt++) {
        const int col = nt * 8 + 2 * tig;
        *(uint32_t*)(Og  + col) = packbf2(oacc[nt][0] * i0, oacc[nt][1] * i0);
        *(uint32_t*)(Og8 + col) = packbf2(oacc[nt][2] * i1, oacc[nt][3] * i1);
    }
}

// ---------------------------------------------------------------------------
// launch
// ---------------------------------------------------------------------------
extern "C" void kernel_launch(void* const* d_in, const int* in_sizes, int n_in,
                              void* d_out, int out_size) {
    const float* x  = (const float*)d_in[0];
    const float* Wq = (const float*)d_in[1];
    const float* Wk = (const float*)d_in[2];
    const float* Wv = (const float*)d_in[3];
    const float* Wo = (const float*)d_in[4];
    const float* qg = (const float*)d_in[5];
    const float* kg = (const float*)d_in[6];
    float* out = (float*)d_out;

    float *pQ, *pK, *pV;
    __nv_bfloat16 *pxb, *pOb, *pWqb, *pWkb, *pWvb, *pWob;
    cudaGetSymbolAddress((void**)&pQ,  g_Q);
    cudaGetSymbolAddress((void**)&pK,  g_K);
    cudaGetSymbolAddress((void**)&pV,  g_V);
    cudaGetSymbolAddress((void**)&pxb, g_xb);
    cudaGetSymbolAddress((void**)&pOb, g_Ob);
    cudaGetSymbolAddress((void**)&pWqb, g_Wqb);
    cudaGetSymbolAddress((void**)&pWkb, g_Wkb);
    cudaGetSymbolAddress((void**)&pWvb, g_Wvb);
    cudaGetSymbolAddress((void**)&pWob, g_Wob);

    const int M = BATCH * SEQ;  // 4096

    // ---- fp32 -> bf16 conversions ----
    {
        const int nx = M * DMODEL / 4;
        cvt_bf16<<<(nx + 255) / 256, 256>>>((const float4*)x,  (uint32_t*)pxb,  nx);
        const int nq = DMODEL * DMODEL / 4;
        cvt_bf16<<<(nq + 255) / 256, 256>>>((const float4*)Wq, (uint32_t*)pWqb, nq);
        const int nk = DMODEL * KVD / 4;
        cvt_bf16<<<(nk + 255) / 256, 256>>>((const float4*)Wk, (uint32_t*)pWkb, nk);
        cvt_bf16<<<(nk + 255) / 256, 256>>>((const float4*)Wv, (uint32_t*)pWvb, nk);
        cvt_bf16<<<(nq + 255) / 256, 256>>>((const float4*)Wo, (uint32_t*)pWob, nq);
    }

    cudaFuncSetAttribute(gemm_bf16_tc, cudaFuncAttributeMaxDynamicSharedMemorySize,
                         GEMM_SMEM_BYTES);

    // QKV projections
    gemm_bf16_tc<<<dim3(DMODEL / 128, M / 128), 256, GEMM_SMEM_BYTES>>>(
        M, DMODEL, DMODEL, pxb, pWqb, nullptr, pQ);
    gemm_bf16_tc<<<dim3(KVD / 128, M / 128), 256, GEMM_SMEM_BYTES>>>(
        M, KVD, DMODEL, pxb, pWkb, nullptr, pK);
    gemm_bf16_tc<<<dim3(KVD / 128, M / 128), 256, GEMM_SMEM_BYTES>>>(
        M, KVD, DMODEL, pxb, pWvb, nullptr, pV);

    // per-head RMSNorm
    rmsnorm128<<<(M * NHEAD) / 8, 256>>>(pQ, qg, M * NHEAD);
    rmsnorm128<<<(M * NKVH)  / 8, 256>>>(pK, kg, M * NKVH);

    // causal GQA flash attention (bf16 mma), writes bf16 O
    const size_t fsmem = FA_SMEM_U32 * sizeof(uint32_t);
    cudaFuncSetAttribute(flash_bf16, cudaFuncAttributeMaxDynamicSharedMemorySize, (int)fsmem);
    flash_bf16<<<dim3(SEQ / 128, NHEAD, BATCH), 256, fsmem>>>(pQ, pK, pV, pOb);

    // output projection + residual
    gemm_bf16_tc<<<dim3(DMODEL / 128, M / 128), 256, GEMM_SMEM_BYTES>>>(
        M, DMODEL, DMODEL, pOb, pWob, x, out);
}

// round 8
// speedup vs baseline: 10.6438x; 1.1504x over previous
#include <cuda_runtime.h>
#include <cuda_bf16.h>
#include <cstdint>

// ---------------------------------------------------------------------------
// Problem constants
// ---------------------------------------------------------------------------
#define BATCH 2
#define SEQ   2048
#define DMODEL 2048
#define KVD    512
#define NHEAD  16
#define NKVH   4
#define DHEAD  128
#define QKV_N   3072          // fused QKV output width (bf16)
#define KOFF    2048          // K column offset in fused buffer
#define VOFF    2560          // V column offset

// Scratch buffers (allocation-free rule: __device__ globals)
__device__ __nv_bfloat16 g_xb  [BATCH * SEQ * DMODEL];      // x in bf16
__device__ __nv_bfloat16 g_QKVb[BATCH * SEQ * QKV_N];       // fused QKV (bf16)
__device__ __nv_bfloat16 g_Ob  [BATCH * SEQ * DMODEL];      // attention out (bf16)
__device__ __nv_bfloat16 g_Wcat[DMODEL * QKV_N];            // [Wq | Wk | Wv] bf16
__device__ __nv_bfloat16 g_Wob [DMODEL * DMODEL];

__device__ __forceinline__ uint32_t packbf2(float lo, float hi) {
    __nv_bfloat162 h = __floats2bfloat162_rn(lo, hi);
    return *reinterpret_cast<uint32_t*>(&h);
}
__device__ __forceinline__ uint32_t mulbf2(uint32_t a, uint32_t s) {
    __nv_bfloat162 x = *reinterpret_cast<__nv_bfloat162*>(&a);
    __nv_bfloat162 y = *reinterpret_cast<__nv_bfloat162*>(&s);
    __nv_bfloat162 r = __hmul2(x, y);
    return *reinterpret_cast<uint32_t*>(&r);
}
__device__ __forceinline__ uint32_t smem_u32(const void* p) {
    return (uint32_t)__cvta_generic_to_shared(p);
}
__device__ __forceinline__ void cp16(void* dst, const void* src) {
    asm volatile("cp.async.cg.shared.global [%0], [%1], 16;"
                 :: "r"(smem_u32(dst)), "l"(src));
}
#define CP_COMMIT() asm volatile("cp.async.commit_group;")
#define CP_WAIT1()  asm volatile("cp.async.wait_group 1;")
#define CP_WAIT0()  asm volatile("cp.async.wait_group 0;")

__device__ __forceinline__ void ldsm_x4(uint32_t r[4], uint32_t addr) {
    asm volatile("ldmatrix.sync.aligned.m8n8.x4.shared.b16 {%0,%1,%2,%3}, [%4];"
                 : "=r"(r[0]), "=r"(r[1]), "=r"(r[2]), "=r"(r[3]) : "r"(addr));
}
__device__ __forceinline__ void ldsm_x4_t(uint32_t r[4], uint32_t addr) {
    asm volatile("ldmatrix.sync.aligned.m8n8.x4.trans.shared.b16 {%0,%1,%2,%3}, [%4];"
                 : "=r"(r[0]), "=r"(r[1]), "=r"(r[2]), "=r"(r[3]) : "r"(addr));
}
__device__ __forceinline__ void mma_bf16(float c[4], const uint32_t a[4], const uint32_t b[2]) {
    asm volatile(
        "mma.sync.aligned.m16n8k16.row.col.f32.bf16.bf16.f32 "
        "{%0,%1,%2,%3}, {%4,%5,%6,%7}, {%8,%9}, {%0,%1,%2,%3};\n"
        : "+f"(c[0]), "+f"(c[1]), "+f"(c[2]), "+f"(c[3])
        : "r"(a[0]), "r"(a[1]), "r"(a[2]), "r"(a[3]),
          "r"(b[0]), "r"(b[1]));
}

// ---------------------------------------------------------------------------
// fp32 -> bf16 conversion (flat)
// ---------------------------------------------------------------------------
__global__ __launch_bounds__(256)
void cvt_bf16(const float4* __restrict__ src, uint32_t* __restrict__ dst, int n4) {
    const int i = blockIdx.x * blockDim.x + threadIdx.x;
    if (i >= n4) return;
    const float4 v = src[i];
    dst[2 * i]     = packbf2(v.x, v.y);
    dst[2 * i + 1] = packbf2(v.z, v.w);
}

// fp32 [2048][C] -> bf16 slice of g_Wcat (row stride QKV_N) at colOff
__global__ __launch_bounds__(256)
void cvt_bf16_cat(const float* __restrict__ src, __nv_bfloat16* __restrict__ dst,
                  int C, int colOff) {
    const int i = blockIdx.x * blockDim.x + threadIdx.x;
    const int n8 = C / 8;
    const int row = i / n8, c8 = (i - row * n8) * 8;
    if (row >= DMODEL) return;
    const float4 a = *(const float4*)(src + (size_t)row * C + c8);
    const float4 b = *(const float4*)(src + (size_t)row * C + c8 + 4);
    uint32_t* d = (uint32_t*)(dst + (size_t)row * QKV_N + colOff + c8);
    d[0] = packbf2(a.x, a.y); d[1] = packbf2(a.z, a.w);
    d[2] = packbf2(b.x, b.y); d[3] = packbf2(b.z, b.w);
}

// ---------------------------------------------------------------------------
// BF16 tensor-core GEMM, cp.async + ldmatrix, 3-stage pipeline.
// Templated output: bf16 (QKV) or fp32 + residual (final projection).
// ---------------------------------------------------------------------------
#define AST 40
#define BST 136
#define A_STG (128 * AST)
#define B_STG (32 * BST)
#define STG_ELEMS (A_STG + B_STG)
#define GEMM_SMEM_BYTES (3 * STG_ELEMS * 2)

template<bool BOUT>
__global__ __launch_bounds__(256)
void gemm_tc(int M, int N, int K,
             const __nv_bfloat16* __restrict__ A,
             const __nv_bfloat16* __restrict__ B,
             const float* __restrict__ R,
             float* __restrict__ Cf,
             __nv_bfloat16* __restrict__ Cb) {
    extern __shared__ __nv_bfloat16 smb[];

    const int tid  = threadIdx.x;
    const int lane = tid & 31;
    const int wid  = tid >> 5;
    const int warpRow = wid & 1;
    const int warpCol = wid >> 1;
    const int grp = lane >> 2;
    const int tig = lane & 3;
    const size_t bm = (size_t)blockIdx.y * 128;
    const size_t bn = (size_t)blockIdx.x * 128;

    const int lrow = (lane & 7) + (lane & 8);
    const int lcol8 = ((lane >> 4) << 3);

    float acc[4][4][4];
    #pragma unroll
    for (int i = 0; i < 4; i++)
        #pragma unroll
        for (int j = 0; j < 4; j++)
            #pragma unroll
            for (int q = 0; q < 4; q++) acc[i][j][q] = 0.f;

    const int T = K / 32;

    auto issue = [&](int stage, int k0) {
        __nv_bfloat16* As = smb + stage * STG_ELEMS;
        __nv_bfloat16* Bs = As + A_STG;
        #pragma unroll
        for (int t = 0; t < 2; t++) {
            const int c = tid + t * 256;
            const int ar = c >> 2, akc = (c & 3) * 8;
            cp16(As + ar * AST + akc, A + (bm + ar) * K + k0 + akc);
            const int br = c >> 4, bnc = (c & 15) * 8;
            cp16(Bs + br * BST + bnc, B + (size_t)(k0 + br) * N + bn + bnc);
        }
        CP_COMMIT();
    };

    issue(0, 0);
    issue(1, 32);

    for (int i = 0; i < T; i++) {
        CP_WAIT1();
        __syncthreads();
        if (i + 2 < T) issue((i + 2) % 3, (i + 2) * 32);

        const __nv_bfloat16* As = smb + (i % 3) * STG_ELEMS;
        const __nv_bfloat16* Bs = As + A_STG;
        const uint32_t sA = smem_u32(As);
        const uint32_t sB = smem_u32(Bs);

        #pragma unroll
        for (int ks = 0; ks < 2; ks++) {
            uint32_t afr[4][4];
            #pragma unroll
            for (int mt = 0; mt < 4; mt++) {
                const int r = warpRow * 64 + mt * 16 + lrow;
                ldsm_x4(afr[mt], sA + (uint32_t)(r * AST + ks * 16 + lcol8) * 2);
            }
            uint32_t bfr[4][2];
            #pragma unroll
            for (int half = 0; half < 2; half++) {
                const int brow = ks * 16 + lrow;
                const int ncol = warpCol * 32 + half * 16 + lcol8;
                uint32_t rr[4];
                ldsm_x4_t(rr, sB + (uint32_t)(brow * BST + ncol) * 2);
                bfr[2 * half][0] = rr[0]; bfr[2 * half][1] = rr[1];
                bfr[2 * half + 1][0] = rr[2]; bfr[2 * half + 1][1] = rr[3];
            }
            #pragma unroll
            for (int mt = 0; mt < 4; mt++)
                #pragma unroll
                for (int nt = 0; nt < 4; nt++)
                    mma_bf16(acc[mt][nt], afr[mt], bfr[nt]);
        }
    }

    #pragma unroll
    for (int mt = 0; mt < 4; mt++) {
        #pragma unroll
        for (int nt = 0; nt < 4; nt++) {
            const int row = (int)bm + warpRow * 64 + mt * 16 + grp;
            const int col = (int)bn + warpCol * 32 + nt * 8 + 2 * tig;
            if (BOUT) {
                *(uint32_t*)(Cb + (size_t)row * N + col) =
                    packbf2(acc[mt][nt][0], acc[mt][nt][1]);
                *(uint32_t*)(Cb + (size_t)(row + 8) * N + col) =
                    packbf2(acc[mt][nt][2], acc[mt][nt][3]);
            } else {
                float2 v0 = make_float2(acc[mt][nt][0], acc[mt][nt][1]);
                float2 v1 = make_float2(acc[mt][nt][2], acc[mt][nt][3]);
                const float2 r0 = *(const float2*)(R + (size_t)row * N + col);
                const float2 r1 = *(const float2*)(R + (size_t)(row + 8) * N + col);
                v0.x += r0.x; v0.y += r0.y;
                v1.x += r1.x; v1.y += r1.y;
                *(float2*)(Cf + (size_t)row * N + col) = v0;
                *(float2*)(Cf + (size_t)(row + 8) * N + col) = v1;
            }
        }
    }
}

// ---------------------------------------------------------------------------
// RMSNorm on bf16 vectors of 128 inside the fused QKV buffer.
// One warp per vector; vector w -> row = w >> hshift, head = w & mask.
// ---------------------------------------------------------------------------
__global__ __launch_bounds__(256)
void rmsnorm_bf16(__nv_bfloat16* __restrict__ t, const float* __restrict__ gamma,
                  int nvec, int hshift, int colOff) {
    const int w = (blockIdx.x * blockDim.x + threadIdx.x) >> 5;
    if (w >= nvec) return;
    const int lane = threadIdx.x & 31;
    const int row  = w >> hshift;
    const int head = w & ((1 << hshift) - 1);
    uint2* p = (uint2*)(t + (size_t)row * QKV_N + colOff + head * DHEAD) + lane;
    uint2 v = *p;
    __nv_bfloat162 h0 = *reinterpret_cast<__nv_bfloat162*>(&v.x);
    __nv_bfloat162 h1 = *reinterpret_cast<__nv_bfloat162*>(&v.y);
    const float f0 = __bfloat162float(h0.x), f1 = __bfloat162float(h0.y);
    const float f2 = __bfloat162float(h1.x), f3 = __bfloat162float(h1.y);
    float ss = f0 * f0 + f1 * f1 + f2 * f2 + f3 * f3;
    #pragma unroll
    for (int o = 16; o; o >>= 1) ss += __shfl_xor_sync(0xffffffffu, ss, o);
    const float rs = rsqrtf(ss * (1.0f / 128.0f) + 1e-8f);
    const float4 gg = ((const float4*)gamma)[lane];
    v.x = packbf2(f0 * rs * gg.x, f1 * rs * gg.y);
    v.y = packbf2(f2 * rs * gg.z, f3 * rs * gg.w);
    *p = v;
}

// ---------------------------------------------------------------------------
// BF16 flash attention (causal, GQA), reading the fused bf16 QKV buffer.
// BQ=128 (8 warps x 16 rows), BKV=64, double-buffered cp.async K/V staging.
// K smem rows = raw bf16 row copies (d-pair u32 layout matches B fragments).
// V smem rows = raw copies; B fragments via ldmatrix.x4.trans (GEMM pattern).
// P accumulator packs directly into bf16 A fragments (no shuffles).
// ---------------------------------------------------------------------------
#define KV_ROW_U32 68                       // 64 data u32 (128 bf16) + 4 pad
#define STAGE_U32 (2 * 64 * KV_ROW_U32)     // K + V tile per stage
#define FA_SMEM_U32 (2 * STAGE_U32)         // double buffer

__global__ __launch_bounds__(256, 1)
void flash_bf16(const __nv_bfloat16* __restrict__ QKV,
                __nv_bfloat16* __restrict__ Ob) {
    const int qb = gridDim.x - 1 - (int)blockIdx.x;   // heavy tiles first
    const int h  = blockIdx.y;
    const int b  = blockIdx.z;
    const int kvh = h >> 2;

    extern __shared__ uint32_t smu[];

    const int tid  = threadIdx.x;
    const int lane = tid & 31;
    const int w    = tid >> 5;
    const int grp  = lane >> 2;
    const int tig  = lane & 3;
    const int q0   = qb * 128;
    const int lrow = (lane & 7) + (lane & 8);
    const int lcol8 = ((lane >> 4) << 3);

    const int r0g = q0 + w * 16 + grp;

    // --- Q fragments: direct u32 loads from bf16 buffer, scaled via hmul2 ---
    const uint32_t scale2 = packbf2(0.08838834764831845f, 0.08838834764831845f);
    uint32_t qf[8][4];
    {
        const uint32_t* Qr  = (const uint32_t*)QKV + (size_t)(b * SEQ + r0g) * (QKV_N / 2) + h * (DHEAD / 2);
        const uint32_t* Qr8 = Qr + 8 * (size_t)(QKV_N / 2);
        #pragma unroll
        for (int kt = 0; kt < 8; kt++) {
            qf[kt][0] = mulbf2(Qr [kt * 8 + tig    ], scale2);
            qf[kt][1] = mulbf2(Qr8[kt * 8 + tig    ], scale2);
            qf[kt][2] = mulbf2(Qr [kt * 8 + tig + 4], scale2);
            qf[kt][3] = mulbf2(Qr8[kt * 8 + tig + 4], scale2);
        }
    }

    // --- staging: raw row copies of K and V tiles (8 cp16 per thread) ---
    auto issue_tile = [&](int stage, int kv0) {
        uint32_t* Ks = smu + stage * STAGE_U32;
        uint32_t* Vs = Ks + 64 * KV_ROW_U32;
        const __nv_bfloat16* Kg = QKV + (size_t)(b * SEQ + kv0) * QKV_N + KOFF + kvh * DHEAD;
        const __nv_bfloat16* Vg = QKV + (size_t)(b * SEQ + kv0) * QKV_N + VOFF + kvh * DHEAD;
        #pragma unroll
        for (int t = 0; t < 4; t++) {
            const int c = tid + t * 256;      // 0..1023
            const int row = c >> 4, ch = c & 15;
            cp16(Ks + row * KV_ROW_U32 + ch * 4, Kg + (size_t)row * QKV_N + ch * 8);
            cp16(Vs + row * KV_ROW_U32 + ch * 4, Vg + (size_t)row * QKV_N + ch * 8);
        }
        CP_COMMIT();
    };

    float oacc[16][4];
    #pragma unroll
    for (int i = 0; i < 16; i++)
        #pragma unroll
        for (int q = 0; q < 4; q++) oacc[i][q] = 0.f;
    float m0 = -1e30f, m1 = -1e30f, l0 = 0.f, l1 = 0.f;

    const int ntiles = 2 * qb + 2;
    issue_tile(0, 0);

    for (int t = 0; t < ntiles; t++) {
        const int kv0 = t * 64;
        CP_WAIT0();
        __syncthreads();        // tile t loaded; all warps done with prev buffer
        if (t + 1 < ntiles) issue_tile((t + 1) & 1, (t + 1) * 64);

        const uint32_t* Ks = smu + (t & 1) * STAGE_U32;
        const uint32_t sV = smem_u32(Ks + 64 * KV_ROW_U32);

        // --- S = Q K^T ---
        float s[8][4];
        #pragma unroll
        for (int nt = 0; nt < 8; nt++)
            #pragma unroll
            for (int q = 0; q < 4; q++) s[nt][q] = 0.f;

        #pragma unroll
        for (int kt = 0; kt < 8; kt++) {
            #pragma unroll
            for (int nt = 0; nt < 8; nt++) {
                uint32_t bf[2];
                const uint32_t* kr = Ks + (nt * 8 + grp) * KV_ROW_U32 + kt * 8;
                bf[0] = kr[tig];
                bf[1] = kr[tig + 4];
                mma_bf16(s[nt], qf[kt], bf);
            }
        }

        // --- causal mask ---
        if (t >= 2 * qb) {
            #pragma unroll
            for (int nt = 0; nt < 8; nt++) {
                const int col = kv0 + nt * 8 + 2 * tig;
                if (col     > r0g    ) s[nt][0] = -1e30f;
                if (col + 1 > r0g    ) s[nt][1] = -1e30f;
                if (col     > r0g + 8) s[nt][2] = -1e30f;
                if (col + 1 > r0g + 8) s[nt][3] = -1e30f;
            }
        }

        // --- online softmax ---
        float mx0 = -1e30f, mx1 = -1e30f;
        #pragma unroll
        for (int nt = 0; nt < 8; nt++) {
            mx0 = fmaxf(mx0, fmaxf(s[nt][0], s[nt][1]));
            mx1 = fmaxf(mx1, fmaxf(s[nt][2], s[nt][3]));
        }
        mx0 = fmaxf(mx0, __shfl_xor_sync(0xffffffffu, mx0, 1));
        mx0 = fmaxf(mx0, __shfl_xor_sync(0xffffffffu, mx0, 2));
        mx1 = fmaxf(mx1, __shfl_xor_sync(0xffffffffu, mx1, 1));
        mx1 = fmaxf(mx1, __shfl_xor_sync(0xffffffffu, mx1, 2));

        const float mn0 = fmaxf(m0, mx0);
        const float mn1 = fmaxf(m1, mx1);
        const float al0 = __expf(m0 - mn0);
        const float al1 = __expf(m1 - mn1);

        float ls0 = 0.f, ls1 = 0.f;
        #pragma unroll
        for (int nt = 0; nt < 8; nt++) {
            s[nt][0] = __expf(s[nt][0] - mn0);
            s[nt][1] = __expf(s[nt][1] - mn0);
            s[nt][2] = __expf(s[nt][2] - mn1);
            s[nt][3] = __expf(s[nt][3] - mn1);
            ls0 += s[nt][0] + s[nt][1];
            ls1 += s[nt][2] + s[nt][3];
        }
        ls0 += __shfl_xor_sync(0xffffffffu, ls0, 1);
        ls0 += __shfl_xor_sync(0xffffffffu, ls0, 2);
        ls1 += __shfl_xor_sync(0xffffffffu, ls1, 1);
        ls1 += __shfl_xor_sync(0xffffffffu, ls1, 2);
        l0 = l0 * al0 + ls0;  m0 = mn0;
        l1 = l1 * al1 + ls1;  m1 = mn1;

        #pragma unroll
        for (int nt = 0; nt < 16; nt++) {
            oacc[nt][0] *= al0; oacc[nt][1] *= al0;
            oacc[nt][2] *= al1; oacc[nt][3] *= al1;
        }

        // --- O += P V : A frags from register packs, B frags via ldsm.trans ---
        #pragma unroll
        for (int kc = 0; kc < 4; kc++) {
            uint32_t af[4];
            af[0] = packbf2(s[2 * kc][0],     s[2 * kc][1]);
            af[1] = packbf2(s[2 * kc][2],     s[2 * kc][3]);
            af[2] = packbf2(s[2 * kc + 1][0], s[2 * kc + 1][1]);
            af[3] = packbf2(s[2 * kc + 1][2], s[2 * kc + 1][3]);
            #pragma unroll
            for (int nblk = 0; nblk < 8; nblk++) {
                uint32_t rr[4];
                ldsm_x4_t(rr, sV + (uint32_t)((kc * 16 + lrow) * (KV_ROW_U32 * 4)
                                              + (nblk * 16 + lcol8) * 2));
                mma_bf16(oacc[2 * nblk],     af, rr);
                mma_bf16(oacc[2 * nblk + 1], af, rr + 2);
            }
        }
    }

    // --- epilogue: normalize, write bf16 O ---
    const float i0 = 1.0f / l0;
    const float i1 = 1.0f / l1;
    __nv_bfloat16* Og  = Ob + ((size_t)(b * SEQ + r0g) * DMODEL) + h * DHEAD;
    __nv_bfloat16* Og8 = Og + 8 * (size_t)DMODEL;
    #pragma unroll
    for (int nt = 0; nt < 16; nt++) {
        const int col = nt * 8 + 2 * tig;
        *(uint32_t*)(Og  + col) = packbf2(oacc[nt][0] * i0, oacc[nt][1] * i0);
        *(uint32_t*)(Og8 + col) = packbf2(oacc[nt][2] * i1, oacc[nt][3] * i1);
    }
}

// ---------------------------------------------------------------------------
// launch
// ---------------------------------------------------------------------------
extern "C" void kernel_launch(void* const* d_in, const int* in_sizes, int n_in,
                              void* d_out, int out_size) {
    const float* x  = (const float*)d_in[0];
    const float* Wq = (const float*)d_in[1];
    const float* Wk = (const float*)d_in[2];
    const float* Wv = (const float*)d_in[3];
    const float* Wo = (const float*)d_in[4];
    const float* qg = (const float*)d_in[5];
    const float* kg = (const float*)d_in[6];
    float* out = (float*)d_out;

    __nv_bfloat16 *pxb, *pQKV, *pOb, *pWcat, *pWob;
    cudaGetSymbolAddress((void**)&pxb,  g_xb);
    cudaGetSymbolAddress((void**)&pQKV, g_QKVb);
    cudaGetSymbolAddress((void**)&pOb,  g_Ob);
    cudaGetSymbolAddress((void**)&pWcat, g_Wcat);
    cudaGetSymbolAddress((void**)&pWob,  g_Wob);

    const int M = BATCH * SEQ;  // 4096

    // ---- conversions ----
    {
        const int nx = M * DMODEL / 4;
        cvt_bf16<<<(nx + 255) / 256, 256>>>((const float4*)x,  (uint32_t*)pxb,  nx);
        const int nq8 = DMODEL * DMODEL / 8;
        cvt_bf16_cat<<<(nq8 + 255) / 256, 256>>>(Wq, pWcat, DMODEL, 0);
        const int nk8 = DMODEL * KVD / 8;
        cvt_bf16_cat<<<(nk8 + 255) / 256, 256>>>(Wk, pWcat, KVD, KOFF);
        cvt_bf16_cat<<<(nk8 + 255) / 256, 256>>>(Wv, pWcat, KVD, VOFF);
        const int nq4 = DMODEL * DMODEL / 4;
        cvt_bf16<<<(nq4 + 255) / 256, 256>>>((const float4*)Wo, (uint32_t*)pWob, nq4);
    }

    cudaFuncSetAttribute(gemm_tc<true>,  cudaFuncAttributeMaxDynamicSharedMemorySize, GEMM_SMEM_BYTES);
    cudaFuncSetAttribute(gemm_tc<false>, cudaFuncAttributeMaxDynamicSharedMemorySize, GEMM_SMEM_BYTES);

    // fused QKV projection (bf16 out)
    gemm_tc<true><<<dim3(QKV_N / 128, M / 128), 256, GEMM_SMEM_BYTES>>>(
        M, QKV_N, DMODEL, pxb, pWcat, nullptr, nullptr, pQKV);

    // per-head RMSNorm (bf16, in fused buffer)
    rmsnorm_bf16<<<(M * NHEAD) / 8, 256>>>(pQKV, qg, M * NHEAD, 4, 0);
    rmsnorm_bf16<<<(M * NKVH)  / 8, 256>>>(pQKV, kg, M * NKVH,  2, KOFF);

    // causal GQA flash attention (bf16), writes bf16 O
    const size_t fsmem = FA_SMEM_U32 * sizeof(uint32_t);
    cudaFuncSetAttribute(flash_bf16, cudaFuncAttributeMaxDynamicSharedMemorySize, (int)fsmem);
    flash_bf16<<<dim3(SEQ / 128, NHEAD, BATCH), 256, fsmem>>>(pQKV, pOb);

    // output projection + residual (fp32 out)
    gemm_tc<false><<<dim3(DMODEL / 128, M / 128), 256, GEMM_SMEM_BYTES>>>(
        M, DMODEL, DMODEL, pOb, pWob, x, out, nullptr);
}

// round 9
// speedup vs baseline: 10.6819x; 1.0036x over previous
#include <cuda_runtime.h>
#include <cuda_bf16.h>
#include <cstdint>

// ---------------------------------------------------------------------------
// Problem constants
// ---------------------------------------------------------------------------
#define BATCH 2
#define SEQ   2048
#define DMODEL 2048
#define KVD    512
#define NHEAD  16
#define NKVH   4
#define DHEAD  128
#define QKV_N   3072
#define KOFF    2048
#define VOFF    2560

// Scratch buffers (allocation-free rule: __device__ globals)
__device__ __nv_bfloat16 g_xb  [BATCH * SEQ * DMODEL];
__device__ __nv_bfloat16 g_QKVb[BATCH * SEQ * QKV_N];
__device__ __nv_bfloat16 g_Ob  [BATCH * SEQ * DMODEL];
__device__ __nv_bfloat16 g_Wcat[DMODEL * QKV_N];
__device__ __nv_bfloat16 g_Wob [DMODEL * DMODEL];

__device__ __forceinline__ uint32_t packbf2(float lo, float hi) {
    __nv_bfloat162 h = __floats2bfloat162_rn(lo, hi);
    return *reinterpret_cast<uint32_t*>(&h);
}
__device__ __forceinline__ uint32_t mulbf2(uint32_t a, uint32_t s) {
    __nv_bfloat162 x = *reinterpret_cast<__nv_bfloat162*>(&a);
    __nv_bfloat162 y = *reinterpret_cast<__nv_bfloat162*>(&s);
    __nv_bfloat162 r = __hmul2(x, y);
    return *reinterpret_cast<uint32_t*>(&r);
}
__device__ __forceinline__ uint32_t smem_u32(const void* p) {
    return (uint32_t)__cvta_generic_to_shared(p);
}
__device__ __forceinline__ void cp16(void* dst, const void* src) {
    asm volatile("cp.async.cg.shared.global [%0], [%1], 16;"
                 :: "r"(smem_u32(dst)), "l"(src));
}
#define CP_COMMIT() asm volatile("cp.async.commit_group;")
#define CP_WAIT1()  asm volatile("cp.async.wait_group 1;")
#define CP_WAIT0()  asm volatile("cp.async.wait_group 0;")

__device__ __forceinline__ void ldsm_x4(uint32_t r[4], uint32_t addr) {
    asm volatile("ldmatrix.sync.aligned.m8n8.x4.shared.b16 {%0,%1,%2,%3}, [%4];"
                 : "=r"(r[0]), "=r"(r[1]), "=r"(r[2]), "=r"(r[3]) : "r"(addr));
}
__device__ __forceinline__ void ldsm_x4_t(uint32_t r[4], uint32_t addr) {
    asm volatile("ldmatrix.sync.aligned.m8n8.x4.trans.shared.b16 {%0,%1,%2,%3}, [%4];"
                 : "=r"(r[0]), "=r"(r[1]), "=r"(r[2]), "=r"(r[3]) : "r"(addr));
}
__device__ __forceinline__ void mma_bf16(float c[4], const uint32_t a[4], const uint32_t b[2]) {
    asm volatile(
        "mma.sync.aligned.m16n8k16.row.col.f32.bf16.bf16.f32 "
        "{%0,%1,%2,%3}, {%4,%5,%6,%7}, {%8,%9}, {%0,%1,%2,%3};\n"
        : "+f"(c[0]), "+f"(c[1]), "+f"(c[2]), "+f"(c[3])
        : "r"(a[0]), "r"(a[1]), "r"(a[2]), "r"(a[3]),
          "r"(b[0]), "r"(b[1]));
}

// ---------------------------------------------------------------------------
// conversions
// ---------------------------------------------------------------------------
__global__ __launch_bounds__(256)
void cvt_bf16(const float4* __restrict__ src, uint32_t* __restrict__ dst, int n4) {
    const int i = blockIdx.x * blockDim.x + threadIdx.x;
    if (i >= n4) return;
    const float4 v = src[i];
    dst[2 * i]     = packbf2(v.x, v.y);
    dst[2 * i + 1] = packbf2(v.z, v.w);
}

// fused: [Wq | Wk | Wv] fp32 -> g_Wcat bf16 (row stride QKV_N)
__global__ __launch_bounds__(256)
void cvt_wcat(const float* __restrict__ Wq, const float* __restrict__ Wk,
              const float* __restrict__ Wv, __nv_bfloat16* __restrict__ dst) {
    const int i = blockIdx.x * blockDim.x + threadIdx.x;   // 8 cols each
    const int row = i / (QKV_N / 8);
    const int c8  = (i - row * (QKV_N / 8)) * 8;
    if (row >= DMODEL) return;
    const float* src;
    if (c8 < KOFF)       src = Wq + (size_t)row * DMODEL + c8;
    else if (c8 < VOFF)  src = Wk + (size_t)row * KVD + (c8 - KOFF);
    else                 src = Wv + (size_t)row * KVD + (c8 - VOFF);
    const float4 a = *(const float4*)(src);
    const float4 b = *(const float4*)(src + 4);
    uint32_t* d = (uint32_t*)(dst + (size_t)row * QKV_N + c8);
    d[0] = packbf2(a.x, a.y); d[1] = packbf2(a.z, a.w);
    d[2] = packbf2(b.x, b.y); d[3] = packbf2(b.z, b.w);
}

// ---------------------------------------------------------------------------
// BF16 tensor-core GEMM, cp.async + ldmatrix, BK=64, 3-stage pipeline.
// Templated output: bf16 (QKV) or fp32 + residual (final projection).
// smem: As bf16[128][72] (9r mod 8 bijective), Bs bf16[64][136] (17r mod 8).
// ---------------------------------------------------------------------------
#define AST 72
#define BST 136
#define A_STG (128 * AST)            // 9216 bf16
#define B_STG (64 * BST)             // 8704 bf16
#define STG_ELEMS (A_STG + B_STG)    // 17920 bf16 = 35840 B
#define GEMM_SMEM_BYTES (3 * STG_ELEMS * 2)   // 107520

template<bool BOUT>
__global__ __launch_bounds__(256, 2)
void gemm_tc(int M, int N, int K,
             const __nv_bfloat16* __restrict__ A,
             const __nv_bfloat16* __restrict__ B,
             const float* __restrict__ R,
             float* __restrict__ Cf,
             __nv_bfloat16* __restrict__ Cb) {
    extern __shared__ __nv_bfloat16 smb[];

    const int tid  = threadIdx.x;
    const int lane = tid & 31;
    const int wid  = tid >> 5;
    const int warpRow = wid & 1;
    const int warpCol = wid >> 1;
    const int grp = lane >> 2;
    const int tig = lane & 3;
    const size_t bm = (size_t)blockIdx.y * 128;
    const size_t bn = (size_t)blockIdx.x * 128;

    const int lrow = (lane & 7) + (lane & 8);
    const int lcol8 = ((lane >> 4) << 3);

    float acc[4][4][4];
    #pragma unroll
    for (int i = 0; i < 4; i++)
        #pragma unroll
        for (int j = 0; j < 4; j++)
            #pragma unroll
            for (int q = 0; q < 4; q++) acc[i][j][q] = 0.f;

    const int T = K / 64;

    auto issue = [&](int stage, int k0) {
        __nv_bfloat16* As = smb + stage * STG_ELEMS;
        __nv_bfloat16* Bs = As + A_STG;
        #pragma unroll
        for (int t = 0; t < 4; t++) {
            const int c = tid + t * 256;                 // 0..1023
            const int ar = c >> 3, akc = (c & 7) * 8;    // A: 128 rows x 64 k
            cp16(As + ar * AST + akc, A + (bm + ar) * K + k0 + akc);
            const int br = c >> 4, bnc = (c & 15) * 8;   // B: 64 rows x 128 n
            cp16(Bs + br * BST + bnc, B + (size_t)(k0 + br) * N + bn + bnc);
        }
        CP_COMMIT();
    };

    issue(0, 0);
    issue(1, 64);

    for (int i = 0; i < T; i++) {
        CP_WAIT1();
        __syncthreads();
        if (i + 2 < T) issue((i + 2) % 3, (i + 2) * 64);

        const __nv_bfloat16* As = smb + (i % 3) * STG_ELEMS;
        const __nv_bfloat16* Bs = As + A_STG;
        const uint32_t sA = smem_u32(As);
        const uint32_t sB = smem_u32(Bs);

        #pragma unroll
        for (int ks = 0; ks < 4; ks++) {
            uint32_t afr[4][4];
            #pragma unroll
            for (int mt = 0; mt < 4; mt++) {
                const int r = warpRow * 64 + mt * 16 + lrow;
                ldsm_x4(afr[mt], sA + (uint32_t)(r * AST + ks * 16 + lcol8) * 2);
            }
            uint32_t bfr[4][2];
            #pragma unroll
            for (int half = 0; half < 2; half++) {
                const int brow = ks * 16 + lrow;
                const int ncol = warpCol * 32 + half * 16 + lcol8;
                uint32_t rr[4];
                ldsm_x4_t(rr, sB + (uint32_t)(brow * BST + ncol) * 2);
                bfr[2 * half][0] = rr[0]; bfr[2 * half][1] = rr[1];
                bfr[2 * half + 1][0] = rr[2]; bfr[2 * half + 1][1] = rr[3];
            }
            #pragma unroll
            for (int mt = 0; mt < 4; mt++)
                #pragma unroll
                for (int nt = 0; nt < 4; nt++)
                    mma_bf16(acc[mt][nt], afr[mt], bfr[nt]);
        }
    }

    #pragma unroll
    for (int mt = 0; mt < 4; mt++) {
        #pragma unroll
        for (int nt = 0; nt < 4; nt++) {
            const int row = (int)bm + warpRow * 64 + mt * 16 + grp;
            const int col = (int)bn + warpCol * 32 + nt * 8 + 2 * tig;
            if (BOUT) {
                *(uint32_t*)(Cb + (size_t)row * N + col) =
                    packbf2(acc[mt][nt][0], acc[mt][nt][1]);
                *(uint32_t*)(Cb + (size_t)(row + 8) * N + col) =
                    packbf2(acc[mt][nt][2], acc[mt][nt][3]);
            } else {
                float2 v0 = make_float2(acc[mt][nt][0], acc[mt][nt][1]);
                float2 v1 = make_float2(acc[mt][nt][2], acc[mt][nt][3]);
                const float2 r0 = *(const float2*)(R + (size_t)row * N + col);
                const float2 r1 = *(const float2*)(R + (size_t)(row + 8) * N + col);
                v0.x += r0.x; v0.y += r0.y;
                v1.x += r1.x; v1.y += r1.y;
                *(float2*)(Cf + (size_t)row * N + col) = v0;
                *(float2*)(Cf + (size_t)(row + 8) * N + col) = v1;
            }
        }
    }
}

// ---------------------------------------------------------------------------
// Merged RMSNorm (Q and K heads, bf16, inside fused QKV buffer).
// One warp per 128-vector. First M*NHEAD warps: Q; next M*NKVH: K.
// ---------------------------------------------------------------------------
__global__ __launch_bounds__(256)
void rmsnorm_qk(__nv_bfloat16* __restrict__ t, const float* __restrict__ qg,
                const float* __restrict__ kg) {
    const int w = (blockIdx.x * blockDim.x + threadIdx.x) >> 5;
    const int NQ = BATCH * SEQ * NHEAD;
    const int NK = BATCH * SEQ * NKVH;
    if (w >= NQ + NK) return;
    const int lane = threadIdx.x & 31;
    size_t off;
    const float* gamma;
    if (w < NQ) {
        off = (size_t)(w >> 4) * QKV_N + (w & 15) * DHEAD;
        gamma = qg;
    } else {
        const int w2 = w - NQ;
        off = (size_t)(w2 >> 2) * QKV_N + KOFF + (w2 & 3) * DHEAD;
        gamma = kg;
    }
    uint2* p = (uint2*)(t + off) + lane;
    uint2 v = *p;
    __nv_bfloat162 h0 = *reinterpret_cast<__nv_bfloat162*>(&v.x);
    __nv_bfloat162 h1 = *reinterpret_cast<__nv_bfloat162*>(&v.y);
    const float f0 = __bfloat162float(h0.x), f1 = __bfloat162float(h0.y);
    const float f2 = __bfloat162float(h1.x), f3 = __bfloat162float(h1.y);
    float ss = f0 * f0 + f1 * f1 + f2 * f2 + f3 * f3;
    #pragma unroll
    for (int o = 16; o; o >>= 1) ss += __shfl_xor_sync(0xffffffffu, ss, o);
    const float rs = rsqrtf(ss * (1.0f / 128.0f) + 1e-8f);
    const float4 gg = ((const float4*)gamma)[lane];
    v.x = packbf2(f0 * rs * gg.x, f1 * rs * gg.y);
    v.y = packbf2(f2 * rs * gg.z, f3 * rs * gg.w);
    *p = v;
}

// ---------------------------------------------------------------------------
// BF16 flash attention (causal, GQA): K fragments now via ldsm_x4 (non-trans),
// V via ldsm_x4_t; double-buffered cp.async K/V staging; heavy tiles first.
// ---------------------------------------------------------------------------
#define KV_ROW_U32 68
#define STAGE_U32 (2 * 64 * KV_ROW_U32)
#define FA_SMEM_U32 (2 * STAGE_U32)

__global__ __launch_bounds__(256, 1)
void flash_bf16(const __nv_bfloat16* __restrict__ QKV,
                __nv_bfloat16* __restrict__ Ob) {
    const int qb = gridDim.x - 1 - (int)blockIdx.x;
    const int h  = blockIdx.y;
    const int b  = blockIdx.z;
    const int kvh = h >> 2;

    extern __shared__ uint32_t smu[];

    const int tid  = threadIdx.x;
    const int lane = tid & 31;
    const int w    = tid >> 5;
    const int grp  = lane >> 2;
    const int tig  = lane & 3;
    const int q0   = qb * 128;
    const int lrow = (lane & 7) + (lane & 8);
    const int lcol8 = ((lane >> 4) << 3);
    // K B-fragment ldsm addressing (non-trans): n offset + k half
    const int kn_off = (lane & 7) + ((lane >> 4) << 3);
    const int kk_off = ((lane >> 3) & 1) * 8;

    const int r0g = q0 + w * 16 + grp;

    const uint32_t scale2 = packbf2(0.08838834764831845f, 0.08838834764831845f);
    uint32_t qf[8][4];
    {
        const uint32_t* Qr  = (const uint32_t*)QKV + (size_t)(b * SEQ + r0g) * (QKV_N / 2) + h * (DHEAD / 2);
        const uint32_t* Qr8 = Qr + 8 * (size_t)(QKV_N / 2);
        #pragma unroll
        for (int kt = 0; kt < 8; kt++) {
            qf[kt][0] = mulbf2(Qr [kt * 8 + tig    ], scale2);
            qf[kt][1] = mulbf2(Qr8[kt * 8 + tig    ], scale2);
            qf[kt][2] = mulbf2(Qr [kt * 8 + tig + 4], scale2);
            qf[kt][3] = mulbf2(Qr8[kt * 8 + tig + 4], scale2);
        }
    }

    auto issue_tile = [&](int stage, int kv0) {
        uint32_t* Ks = smu + stage * STAGE_U32;
        uint32_t* Vs = Ks + 64 * KV_ROW_U32;
        const __nv_bfloat16* Kg = QKV + (size_t)(b * SEQ + kv0) * QKV_N + KOFF + kvh * DHEAD;
        const __nv_bfloat16* Vg = QKV + (size_t)(b * SEQ + kv0) * QKV_N + VOFF + kvh * DHEAD;
        #pragma unroll
        for (int t = 0; t < 4; t++) {
            const int c = tid + t * 256;
            const int row = c >> 4, ch = c & 15;
            cp16(Ks + row * KV_ROW_U32 + ch * 4, Kg + (size_t)row * QKV_N + ch * 8);
            cp16(Vs + row * KV_ROW_U32 + ch * 4, Vg + (size_t)row * QKV_N + ch * 8);
        }
        CP_COMMIT();
    };

    float oacc[16][4];
    #pragma unroll
    for (int i = 0; i < 16; i++)
        #pragma unroll
        for (int q = 0; q < 4; q++) oacc[i][q] = 0.f;
    float m0 = -1e30f, m1 = -1e30f, l0 = 0.f, l1 = 0.f;

    const int ntiles = 2 * qb + 2;
    issue_tile(0, 0);

    for (int t = 0; t < ntiles; t++) {
        const int kv0 = t * 64;
        CP_WAIT0();
        __syncthreads();
        if (t + 1 < ntiles) issue_tile((t + 1) & 1, (t + 1) * 64);

        const uint32_t* Ks = smu + (t & 1) * STAGE_U32;
        const uint32_t sK = smem_u32(Ks);
        const uint32_t sV = smem_u32(Ks + 64 * KV_ROW_U32);

        // --- S = Q K^T : K B-fragments via ldsm_x4 (2 n-tiles per ldsm) ---
        float s[8][4];
        #pragma unroll
        for (int nt = 0; nt < 8; nt++)
            #pragma unroll
            for (int q = 0; q < 4; q++) s[nt][q] = 0.f;

        #pragma unroll
        for (int kt = 0; kt < 8; kt++) {
            #pragma unroll
            for (int np = 0; np < 4; np++) {
                uint32_t rr[4];
                ldsm_x4(rr, sK + (uint32_t)((np * 16 + kn_off) * (KV_ROW_U32 * 4)
                                            + (kt * 16 + kk_off) * 2));
                mma_bf16(s[2 * np],     qf[kt], rr);
                mma_bf16(s[2 * np + 1], qf[kt], rr + 2);
            }
        }

        // --- causal mask ---
        if (t >= 2 * qb) {
            #pragma unroll
            for (int nt = 0; nt < 8; nt++) {
                const int col = kv0 + nt * 8 + 2 * tig;
                if (col     > r0g    ) s[nt][0] = -1e30f;
                if (col + 1 > r0g    ) s[nt][1] = -1e30f;
                if (col     > r0g + 8) s[nt][2] = -1e30f;
                if (col + 1 > r0g + 8) s[nt][3] = -1e30f;
            }
        }

        // --- online softmax ---
        float mx0 = -1e30f, mx1 = -1e30f;
        #pragma unroll
        for (int nt = 0; nt < 8; nt++) {
            mx0 = fmaxf(mx0, fmaxf(s[nt][0], s[nt][1]));
            mx1 = fmaxf(mx1, fmaxf(s[nt][2], s[nt][3]));
        }
        mx0 = fmaxf(mx0, __shfl_xor_sync(0xffffffffu, mx0, 1));
        mx0 = fmaxf(mx0, __shfl_xor_sync(0xffffffffu, mx0, 2));
        mx1 = fmaxf(mx1, __shfl_xor_sync(0xffffffffu, mx1, 1));
        mx1 = fmaxf(mx1, __shfl_xor_sync(0xffffffffu, mx1, 2));

        const float mn0 = fmaxf(m0, mx0);
        const float mn1 = fmaxf(m1, mx1);
        const float al0 = __expf(m0 - mn0);
        const float al1 = __expf(m1 - mn1);

        float ls0 = 0.f, ls1 = 0.f;
        #pragma unroll
        for (int nt = 0; nt < 8; nt++) {
            s[nt][0] = __expf(s[nt][0] - mn0);
            s[nt][1] = __expf(s[nt][1] - mn0);
            s[nt][2] = __expf(s[nt][2] - mn1);
            s[nt][3] = __expf(s[nt][3] - mn1);
            ls0 += s[nt][0] + s[nt][1];
            ls1 += s[nt][2] + s[nt][3];
        }
        ls0 += __shfl_xor_sync(0xffffffffu, ls0, 1);
        ls0 += __shfl_xor_sync(0xffffffffu, ls0, 2);
        ls1 += __shfl_xor_sync(0xffffffffu, ls1, 1);
        ls1 += __shfl_xor_sync(0xffffffffu, ls1, 2);
        l0 = l0 * al0 + ls0;  m0 = mn0;
        l1 = l1 * al1 + ls1;  m1 = mn1;

        #pragma unroll
        for (int nt = 0; nt < 16; nt++) {
            oacc[nt][0] *= al0; oacc[nt][1] *= al0;
            oacc[nt][2] *= al1; oacc[nt][3] *= al1;
        }

        // --- O += P V ---
        #pragma unroll
        for (int kc = 0; kc < 4; kc++) {
            uint32_t af[4];
            af[0] = packbf2(s[2 * kc][0],     s[2 * kc][1]);
            af[1] = packbf2(s[2 * kc][2],     s[2 * kc][3]);
            af[2] = packbf2(s[2 * kc + 1][0], s[2 * kc + 1][1]);
            af[3] = packbf2(s[2 * kc + 1][2], s[2 * kc + 1][3]);
            #pragma unroll
            for (int nblk = 0; nblk < 8; nblk++) {
                uint32_t rr[4];
                ldsm_x4_t(rr, sV + (uint32_t)((kc * 16 + lrow) * (KV_ROW_U32 * 4)
                                              + (nblk * 16 + lcol8) * 2));
                mma_bf16(oacc[2 * nblk],     af, rr);
                mma_bf16(oacc[2 * nblk + 1], af, rr + 2);
            }
        }
    }

    const float i0 = 1.0f / l0;
    const float i1 = 1.0f / l1;
    __nv_bfloat16* Og  = Ob + ((size_t)(b * SEQ + r0g) * DMODEL) + h * DHEAD;
    __nv_bfloat16* Og8 = Og + 8 * (size_t)DMODEL;
    #pragma unroll
    for (int nt = 0; nt < 16; nt++) {
        const int col = nt * 8 + 2 * tig;
        *(uint32_t*)(Og  + col) = packbf2(oacc[nt][0] * i0, oacc[nt][1] * i0);
        *(uint32_t*)(Og8 + col) = packbf2(oacc[nt][2] * i1, oacc[nt][3] * i1);
    }
}

// ---------------------------------------------------------------------------
// launch
// ---------------------------------------------------------------------------
extern "C" void kernel_launch(void* const* d_in, const int* in_sizes, int n_in,
                              void* d_out, int out_size) {
    const float* x  = (const float*)d_in[0];
    const float* Wq = (const float*)d_in[1];
    const float* Wk = (const float*)d_in[2];
    const float* Wv = (const float*)d_in[3];
    const float* Wo = (const float*)d_in[4];
    const float* qg = (const float*)d_in[5];
    const float* kg = (const float*)d_in[6];
    float* out = (float*)d_out;

    __nv_bfloat16 *pxb, *pQKV, *pOb, *pWcat, *pWob;
    cudaGetSymbolAddress((void**)&pxb,  g_xb);
    cudaGetSymbolAddress((void**)&pQKV, g_QKVb);
    cudaGetSymbolAddress((void**)&pOb,  g_Ob);
    cudaGetSymbolAddress((void**)&pWcat, g_Wcat);
    cudaGetSymbolAddress((void**)&pWob,  g_Wob);

    const int M = BATCH * SEQ;  // 4096

    // ---- conversions (3 launches) ----
    {
        const int nx = M * DMODEL / 4;
        cvt_bf16<<<(nx + 255) / 256, 256>>>((const float4*)x, (uint32_t*)pxb, nx);
        const int nw = DMODEL * QKV_N / 8;
        cvt_wcat<<<(nw + 255) / 256, 256>>>(Wq, Wk, Wv, pWcat);
        const int nq4 = DMODEL * DMODEL / 4;
        cvt_bf16<<<(nq4 + 255) / 256, 256>>>((const float4*)Wo, (uint32_t*)pWob, nq4);
    }

    cudaFuncSetAttribute(gemm_tc<true>,  cudaFuncAttributeMaxDynamicSharedMemorySize, GEMM_SMEM_BYTES);
    cudaFuncSetAttribute(gemm_tc<false>, cudaFuncAttributeMaxDynamicSharedMemorySize, GEMM_SMEM_BYTES);

    // fused QKV projection (bf16 out)
    gemm_tc<true><<<dim3(QKV_N / 128, M / 128), 256, GEMM_SMEM_BYTES>>>(
        M, QKV_N, DMODEL, pxb, pWcat, nullptr, nullptr, pQKV);

    // merged per-head RMSNorm (Q + K)
    {
        const int nvec = M * (NHEAD + NKVH);
        rmsnorm_qk<<<(nvec + 7) / 8, 256>>>(pQKV, qg, kg);
    }

    // causal GQA flash attention (bf16)
    const size_t fsmem = FA_SMEM_U32 * sizeof(uint32_t);
    cudaFuncSetAttribute(flash_bf16, cudaFuncAttributeMaxDynamicSharedMemorySize, (int)fsmem);
    flash_bf16<<<dim3(SEQ / 128, NHEAD, BATCH), 256, fsmem>>>(pQKV, pOb);

    // output projection + residual (fp32 out)
    gemm_tc<false><<<dim3(DMODEL / 128, M / 128), 256, GEMM_SMEM_BYTES>>>(
        M, DMODEL, DMODEL, pOb, pWob, x, out, nullptr);
}